// round 1
// baseline (speedup 1.0000x reference)
#include <cuda_runtime.h>
#include <cstdint>
#include <cstddef>

// Problem constants
#define NB     4
#define NSEQ   4096
#define EDIM   128
#define FFD    512
#define NTOK   (NB * NSEQ)          // 16384 tokens

// ---------------------------------------------------------------------------
// Scratch (static device arrays; no runtime allocation allowed)
// ---------------------------------------------------------------------------
__device__ float g_h   [NTOK * EDIM];       // rmsnorm(x)
__device__ float g_qkv [NTOK * 3 * EDIM];   // [t][384] = q|k|v
__device__ float g_S   [NTOK * EDIM];       // sigmoid(q)
__device__ float g_X   [NTOK * 2 * EDIM];   // [t][256] = exp(k)*v | exp(k)
__device__ float g_C   [NTOK * 2 * EDIM];   // [t][256] = w1 | w2
__device__ float g_att [NTOK * EDIM];
__device__ float g_out1[NTOK * EDIM];
__device__ float g_h2  [NTOK * EDIM];
__device__ float g_t   [NTOK * FFD];        // relu(h2@W1+b1)
__device__ float g_Wqkv[EDIM * 3 * EDIM];   // packed [k][384]

// ---------------------------------------------------------------------------
// Helpers
// ---------------------------------------------------------------------------
__device__ __forceinline__ float tf32r(float x) {
    uint32_t u;
    asm("cvt.rna.tf32.f32 %0, %1;" : "=r"(u) : "f"(x));
    return __uint_as_float(u);
}

__device__ __forceinline__ void mma_tf32(float* c, const float* a, const float* b) {
    asm volatile(
        "mma.sync.aligned.m16n8k8.row.col.f32.tf32.tf32.f32 "
        "{%0,%1,%2,%3}, {%4,%5,%6,%7}, {%8,%9}, {%0,%1,%2,%3};\n"
        : "+f"(c[0]), "+f"(c[1]), "+f"(c[2]), "+f"(c[3])
        : "r"(__float_as_uint(a[0])), "r"(__float_as_uint(a[1])),
          "r"(__float_as_uint(a[2])), "r"(__float_as_uint(a[3])),
          "r"(__float_as_uint(b[0])), "r"(__float_as_uint(b[1])));
}

__device__ __forceinline__ void cp16(float* s, const float* gp) {
    uint32_t sa = (uint32_t)__cvta_generic_to_shared(s);
    asm volatile("cp.async.cg.shared.global [%0], [%1], 16;\n" :: "r"(sa), "l"(gp));
}
__device__ __forceinline__ void cp_commit() {
    asm volatile("cp.async.commit_group;\n" ::: "memory");
}
__device__ __forceinline__ void cp_wait0() {
    asm volatile("cp.async.wait_group 0;\n" ::: "memory");
}

// ---------------------------------------------------------------------------
// RMSNorm: one warp per token (128 elems = 32 lanes x float4)
// ---------------------------------------------------------------------------
__global__ void rmsnorm_kernel(const float* __restrict__ x,
                               const float* __restrict__ gw,
                               float* __restrict__ y) {
    int warp = (blockIdx.x * blockDim.x + threadIdx.x) >> 5;
    int lane = threadIdx.x & 31;
    if (warp >= NTOK) return;
    float4 v = reinterpret_cast<const float4*>(x + (size_t)warp * EDIM)[lane];
    float ss = v.x * v.x + v.y * v.y + v.z * v.z + v.w * v.w;
    #pragma unroll
    for (int o = 16; o > 0; o >>= 1) ss += __shfl_xor_sync(0xffffffffu, ss, o);
    float s = rsqrtf(ss * (1.0f / 128.0f) + 1e-6f);
    float4 g4 = reinterpret_cast<const float4*>(gw)[lane];
    float4 o4 = make_float4(v.x * s * g4.x, v.y * s * g4.y, v.z * s * g4.z, v.w * s * g4.w);
    reinterpret_cast<float4*>(y + (size_t)warp * EDIM)[lane] = o4;
}

// ---------------------------------------------------------------------------
// Pack Wq|Wk|Wv -> [128][384]
// ---------------------------------------------------------------------------
__global__ void pack_wqkv(const float* __restrict__ Wq,
                          const float* __restrict__ Wk,
                          const float* __restrict__ Wv) {
    int i = blockIdx.x * blockDim.x + threadIdx.x;
    if (i >= EDIM * 3 * EDIM) return;
    int k = i / 384, n = i % 384;
    float v = (n < 128) ? Wq[k * 128 + n]
            : (n < 256) ? Wk[k * 128 + n - 128]
                        : Wv[k * 128 + n - 256];
    g_Wqkv[i] = v;
}

// ---------------------------------------------------------------------------
// S = sigmoid(q); X = [exp(k)*v, exp(k)]
// ---------------------------------------------------------------------------
__global__ void sx_kernel() {
    int i = blockIdx.x * blockDim.x + threadIdx.x;
    if (i >= NTOK * EDIM) return;
    int t = i >> 7, e = i & 127;
    const float* row = g_qkv + (size_t)t * 384;
    float q = row[e], k = row[128 + e], v = row[256 + e];
    g_S[i] = 1.0f / (1.0f + expf(-q));
    float kw = expf(k);
    g_X[(size_t)t * 256 + e]       = kw * v;
    g_X[(size_t)t * 256 + 128 + e] = kw;
}

// ---------------------------------------------------------------------------
// att = sigmoid(q) * w1/w2
// ---------------------------------------------------------------------------
__global__ void att_kernel() {
    int i = blockIdx.x * blockDim.x + threadIdx.x;
    if (i >= NTOK * EDIM) return;
    int t = i >> 7, e = i & 127;
    float w1 = g_C[(size_t)t * 256 + e];
    float w2 = g_C[(size_t)t * 256 + 128 + e];
    g_att[i] = g_S[i] * (w1 / w2);
}

// ---------------------------------------------------------------------------
// Big GEMM: per batch  C[j,c] = sum_i exp(-coef*dis[i,j]) * X[i,c]
// M=4096(j), K=4096(i), N=256(c). BM=128, BN=256, BK=32, 512 threads,
// double-buffered smem, exp fused into A-tile staging, B via cp.async.
// ---------------------------------------------------------------------------
__global__ __launch_bounds__(512)
void gemm_big_kernel(const float* __restrict__ dis, const float* __restrict__ alphap) {
    extern __shared__ float sm[];
    constexpr int ASTR = 136, BSTR = 264;
    constexpr int ABUF = 32 * ASTR, BBUF = 32 * BSTR;
    float* As = sm;                 // 2 * ABUF
    float* Bs = sm + 2 * ABUF;      // 2 * BBUF

    const int b  = blockIdx.y;
    const int j0 = blockIdx.x * 128;
    const float* Ab = dis + (size_t)b * NSEQ * NSEQ;
    const float* Xb = g_X + (size_t)b * NSEQ * 256;
    float*       Cb = g_C + (size_t)b * NSEQ * 256;
    const float coef = 12.0f * alphap[0];   // alpha * log2(4096)

    const int tid  = threadIdx.x;
    const int lane = tid & 31, warp = tid >> 5;
    const int wm = warp >> 2, wn = warp & 3;       // 4 x 4 warps
    const int g  = lane >> 2, tg = lane & 3;

    const int ar_r0 = tid >> 5;                    // A stage: 2 rows per thread
    const int ar_c  = (tid & 31) << 2;

    float4 ar[2];
    float acc[2][8][4];
    #pragma unroll
    for (int i = 0; i < 2; i++)
        #pragma unroll
        for (int j = 0; j < 8; j++)
            #pragma unroll
            for (int r = 0; r < 4; r++) acc[i][j][r] = 0.0f;

    // -------- prologue: stage tile 0 --------
    {
        #pragma unroll
        for (int i = 0; i < 4; i++) {
            int id = tid + i * 512;
            int r = id >> 6, c = (id & 63) << 2;
            cp16(Bs + r * BSTR + c, Xb + (size_t)r * 256 + c);
        }
        cp_commit();
        #pragma unroll
        for (int i = 0; i < 2; i++) {
            int r = ar_r0 + i * 16;
            ar[i] = *reinterpret_cast<const float4*>(Ab + (size_t)r * NSEQ + j0 + ar_c);
        }
        #pragma unroll
        for (int i = 0; i < 2; i++) {
            int r = ar_r0 + i * 16;
            float* p = As + r * ASTR + ar_c;
            p[0] = tf32r(__expf(-coef * ar[i].x));
            p[1] = tf32r(__expf(-coef * ar[i].y));
            p[2] = tf32r(__expf(-coef * ar[i].z));
            p[3] = tf32r(__expf(-coef * ar[i].w));
        }
        cp_wait0();
        __syncthreads();
    }

    const int KT = NSEQ / 32;
    for (int kt = 0; kt < KT; ++kt) {
        const int buf = kt & 1;
        const bool more = (kt + 1 < KT);
        if (more) {
            const int k0 = (kt + 1) * 32;
            #pragma unroll
            for (int i = 0; i < 4; i++) {
                int id = tid + i * 512;
                int r = id >> 6, c = (id & 63) << 2;
                cp16(Bs + (buf ^ 1) * BBUF + r * BSTR + c, Xb + (size_t)(k0 + r) * 256 + c);
            }
            cp_commit();
            #pragma unroll
            for (int i = 0; i < 2; i++) {
                int r = ar_r0 + i * 16;
                ar[i] = *reinterpret_cast<const float4*>(Ab + (size_t)(k0 + r) * NSEQ + j0 + ar_c);
            }
        }
        const float* A  = As + buf * ABUF;
        const float* Bm = Bs + buf * BBUF;
        #pragma unroll
        for (int ks = 0; ks < 4; ++ks) {
            const int kr = ks * 8 + tg;
            float a[2][4];
            #pragma unroll
            for (int mt = 0; mt < 2; ++mt) {
                int m = wm * 32 + mt * 16 + g;
                a[mt][0] = A[kr * ASTR + m];
                a[mt][1] = A[kr * ASTR + m + 8];
                a[mt][2] = A[(kr + 4) * ASTR + m];
                a[mt][3] = A[(kr + 4) * ASTR + m + 8];
            }
            float bb[8][2];
            #pragma unroll
            for (int nt = 0; nt < 8; ++nt) {
                int n = wn * 64 + nt * 8 + g;
                bb[nt][0] = Bm[kr * BSTR + n];
                bb[nt][1] = Bm[(kr + 4) * BSTR + n];
            }
            #pragma unroll
            for (int mt = 0; mt < 2; ++mt)
                #pragma unroll
                for (int nt = 0; nt < 8; ++nt)
                    mma_tf32(acc[mt][nt], a[mt], bb[nt]);
        }
        if (more) {
            float* Ad = As + (buf ^ 1) * ABUF;
            #pragma unroll
            for (int i = 0; i < 2; i++) {
                int r = ar_r0 + i * 16;
                float* p = Ad + r * ASTR + ar_c;
                p[0] = tf32r(__expf(-coef * ar[i].x));
                p[1] = tf32r(__expf(-coef * ar[i].y));
                p[2] = tf32r(__expf(-coef * ar[i].z));
                p[3] = tf32r(__expf(-coef * ar[i].w));
            }
            cp_wait0();
        }
        __syncthreads();
    }

    // -------- epilogue --------
    #pragma unroll
    for (int mt = 0; mt < 2; ++mt) {
        const int row0 = j0 + wm * 32 + mt * 16 + g;
        #pragma unroll
        for (int nt = 0; nt < 8; ++nt) {
            const int col = wn * 64 + nt * 8 + tg * 2;
            float* p0 = Cb + (size_t)row0 * 256 + col;
            float* p1 = Cb + (size_t)(row0 + 8) * 256 + col;
            p0[0] = acc[mt][nt][0]; p0[1] = acc[mt][nt][1];
            p1[0] = acc[mt][nt][2]; p1[1] = acc[mt][nt][3];
        }
    }
}

// ---------------------------------------------------------------------------
// Generic small GEMM: C[M,N] = A[M,K] @ B[K,N] (+ epilogue)
// BM=128, BN=64, BK=32, 256 threads, single-buffered smem (tf32-rna staged)
// mode 0: store   1: +res   2: relu(+bias)   3: +bias+res
// ---------------------------------------------------------------------------
__global__ __launch_bounds__(256)
void gemm_small_kernel(const float* __restrict__ A, const float* __restrict__ B,
                       float* __restrict__ C, int K, int N, int mode,
                       const float* __restrict__ bias, const float* __restrict__ res) {
    __shared__ float As[128 * 36];
    __shared__ float Bs[32 * 72];
    const int m0 = blockIdx.x * 128;
    const int n0 = blockIdx.y * 64;
    const int tid = threadIdx.x, lane = tid & 31, warp = tid >> 5;
    const int wm = warp >> 1, wn = warp & 1;        // 4 x 2 warps
    const int g = lane >> 2, tg = lane & 3;

    float acc[2][4][4];
    #pragma unroll
    for (int i = 0; i < 2; i++)
        #pragma unroll
        for (int j = 0; j < 4; j++)
            #pragma unroll
            for (int r = 0; r < 4; r++) acc[i][j][r] = 0.0f;

    for (int k0 = 0; k0 < K; k0 += 32) {
        #pragma unroll
        for (int i = 0; i < 4; i++) {
            int id = tid + i * 256;
            int m = id >> 3, c = (id & 7) << 2;
            float4 v = *reinterpret_cast<const float4*>(A + (size_t)(m0 + m) * K + k0 + c);
            float* p = As + m * 36 + c;
            p[0] = tf32r(v.x); p[1] = tf32r(v.y); p[2] = tf32r(v.z); p[3] = tf32r(v.w);
        }
        #pragma unroll
        for (int i = 0; i < 2; i++) {
            int id = tid + i * 256;
            int k = id >> 4, c = (id & 15) << 2;
            float4 v = *reinterpret_cast<const float4*>(B + (size_t)(k0 + k) * N + n0 + c);
            float* p = Bs + k * 72 + c;
            p[0] = tf32r(v.x); p[1] = tf32r(v.y); p[2] = tf32r(v.z); p[3] = tf32r(v.w);
        }
        __syncthreads();
        #pragma unroll
        for (int ks = 0; ks < 4; ++ks) {
            const int kr = ks * 8 + tg;
            float a[2][4];
            #pragma unroll
            for (int mt = 0; mt < 2; ++mt) {
                int m = wm * 32 + mt * 16 + g;
                a[mt][0] = As[m * 36 + kr];
                a[mt][1] = As[(m + 8) * 36 + kr];
                a[mt][2] = As[m * 36 + kr + 4];
                a[mt][3] = As[(m + 8) * 36 + kr + 4];
            }
            float bb[4][2];
            #pragma unroll
            for (int nt = 0; nt < 4; ++nt) {
                int n = wn * 32 + nt * 8 + g;
                bb[nt][0] = Bs[kr * 72 + n];
                bb[nt][1] = Bs[(kr + 4) * 72 + n];
            }
            #pragma unroll
            for (int mt = 0; mt < 2; ++mt)
                #pragma unroll
                for (int nt = 0; nt < 4; ++nt)
                    mma_tf32(acc[mt][nt], a[mt], bb[nt]);
        }
        __syncthreads();
    }

    #pragma unroll
    for (int mt = 0; mt < 2; ++mt) {
        const int row0 = m0 + wm * 32 + mt * 16 + g;
        #pragma unroll
        for (int nt = 0; nt < 4; ++nt) {
            const int col = n0 + wn * 32 + nt * 8 + tg * 2;
            #pragma unroll
            for (int h = 0; h < 2; ++h) {
                const int row = row0 + h * 8;
                float v0 = acc[mt][nt][h * 2 + 0];
                float v1 = acc[mt][nt][h * 2 + 1];
                if (mode == 1) {
                    v0 += res[(size_t)row * N + col];
                    v1 += res[(size_t)row * N + col + 1];
                } else if (mode == 2) {
                    v0 = fmaxf(v0 + bias[col], 0.0f);
                    v1 = fmaxf(v1 + bias[col + 1], 0.0f);
                } else if (mode == 3) {
                    v0 += bias[col]     + res[(size_t)row * N + col];
                    v1 += bias[col + 1] + res[(size_t)row * N + col + 1];
                }
                C[(size_t)row * N + col]     = v0;
                C[(size_t)row * N + col + 1] = v1;
            }
        }
    }
}

// ---------------------------------------------------------------------------
// Launch
// ---------------------------------------------------------------------------
extern "C" void kernel_launch(void* const* d_in, const int* in_sizes, int n_in,
                              void* d_out, int out_size) {
    const float* x     = (const float*)d_in[0];
    const float* dis   = (const float*)d_in[1];
    const float* g_in  = (const float*)d_in[2];
    const float* g_po  = (const float*)d_in[3];
    const float* Wq    = (const float*)d_in[4];
    const float* Wk    = (const float*)d_in[5];
    const float* Wv    = (const float*)d_in[6];
    const float* alpha = (const float*)d_in[7];
    const float* Wo    = (const float*)d_in[8];
    const float* W1    = (const float*)d_in[9];
    const float* b1    = (const float*)d_in[10];
    const float* W2    = (const float*)d_in[11];
    const float* b2    = (const float*)d_in[12];
    float* out = (float*)d_out;

    float *p_h, *p_qkv, *p_att, *p_out1, *p_h2, *p_t, *p_wqkv;
    cudaGetSymbolAddress((void**)&p_h,    g_h);
    cudaGetSymbolAddress((void**)&p_qkv,  g_qkv);
    cudaGetSymbolAddress((void**)&p_att,  g_att);
    cudaGetSymbolAddress((void**)&p_out1, g_out1);
    cudaGetSymbolAddress((void**)&p_h2,   g_h2);
    cudaGetSymbolAddress((void**)&p_t,    g_t);
    cudaGetSymbolAddress((void**)&p_wqkv, g_Wqkv);

    cudaFuncSetAttribute(gemm_big_kernel,
                         cudaFuncAttributeMaxDynamicSharedMemorySize, 102400);

    const int ew_blocks = (NTOK * EDIM + 255) / 256;

    // 1) pack QKV weights
    pack_wqkv<<<(EDIM * 3 * EDIM + 255) / 256, 256>>>(Wq, Wk, Wv);
    // 2) h = rmsnorm(x, g_in)
    rmsnorm_kernel<<<NTOK / 8, 256>>>(x, g_in, p_h);
    // 3) qkv = h @ [Wq|Wk|Wv]
    gemm_small_kernel<<<dim3(NTOK / 128, 6), 256>>>(p_h, p_wqkv, p_qkv,
                                                    128, 384, 0, nullptr, nullptr);
    // 4) S, X
    sx_kernel<<<ew_blocks, 256>>>();
    // 5) big GEMM: C = exp(-coef*dis)^T @ X  (per batch)
    gemm_big_kernel<<<dim3(NSEQ / 128, NB), 512, 102400>>>(dis, alpha);
    // 6) att = S * w1/w2
    att_kernel<<<ew_blocks, 256>>>();
    // 7) out1 = x + att @ Wo
    gemm_small_kernel<<<dim3(NTOK / 128, 2), 256>>>(p_att, Wo, p_out1,
                                                    128, 128, 1, nullptr, x);
    // 8) h2 = rmsnorm(out1, g_post)
    rmsnorm_kernel<<<NTOK / 8, 256>>>(p_out1, g_po, p_h2);
    // 9) t = relu(h2 @ W1 + b1)
    gemm_small_kernel<<<dim3(NTOK / 128, 8), 256>>>(p_h2, W1, p_t,
                                                    128, 512, 2, b1, nullptr);
    // 10) out = out1 + t @ W2 + b2
    gemm_small_kernel<<<dim3(NTOK / 128, 2), 256>>>(p_t, W2, out,
                                                    512, 128, 3, b2, p_out1);
}

// round 2
// speedup vs baseline: 1.0003x; 1.0003x over previous
#include <cuda_runtime.h>
#include <cstdint>
#include <cstddef>

// Problem constants
#define NB     4
#define NSEQ   4096
#define EDIM   128
#define FFD    512
#define NTOK   (NB * NSEQ)          // 16384 tokens

// ---------------------------------------------------------------------------
// Scratch (static device arrays; no runtime allocation allowed)
// ---------------------------------------------------------------------------
__device__ float g_h   [NTOK * EDIM];       // rmsnorm(x)
__device__ float g_qkv [NTOK * 3 * EDIM];   // [t][384] = q|k|v
__device__ float g_S   [NTOK * EDIM];       // sigmoid(q)
__device__ float g_X   [NTOK * 2 * EDIM];   // [t][256] = exp(k)*v | exp(k)
__device__ float g_C   [NTOK * 2 * EDIM];   // [t][256] = w1 | w2
__device__ float g_att [NTOK * EDIM];
__device__ float g_out1[NTOK * EDIM];
__device__ float g_h2  [NTOK * EDIM];
__device__ float g_t   [NTOK * FFD];        // relu(h2@W1+b1)
__device__ float g_Wqkv[EDIM * 3 * EDIM];   // packed [k][384]

// ---------------------------------------------------------------------------
// Helpers
// ---------------------------------------------------------------------------
__device__ __forceinline__ float tf32r(float x) {
    uint32_t u;
    asm("cvt.rna.tf32.f32 %0, %1;" : "=r"(u) : "f"(x));
    return __uint_as_float(u);
}

__device__ __forceinline__ void mma_tf32(float* c, const float* a, const float* b) {
    asm volatile(
        "mma.sync.aligned.m16n8k8.row.col.f32.tf32.tf32.f32 "
        "{%0,%1,%2,%3}, {%4,%5,%6,%7}, {%8,%9}, {%0,%1,%2,%3};\n"
        : "+f"(c[0]), "+f"(c[1]), "+f"(c[2]), "+f"(c[3])
        : "r"(__float_as_uint(a[0])), "r"(__float_as_uint(a[1])),
          "r"(__float_as_uint(a[2])), "r"(__float_as_uint(a[3])),
          "r"(__float_as_uint(b[0])), "r"(__float_as_uint(b[1])));
}

__device__ __forceinline__ void cp16(float* s, const float* gp) {
    uint32_t sa = (uint32_t)__cvta_generic_to_shared(s);
    asm volatile("cp.async.cg.shared.global [%0], [%1], 16;\n" :: "r"(sa), "l"(gp));
}
__device__ __forceinline__ void cp_commit() {
    asm volatile("cp.async.commit_group;\n" ::: "memory");
}
__device__ __forceinline__ void cp_wait0() {
    asm volatile("cp.async.wait_group 0;\n" ::: "memory");
}

// ---------------------------------------------------------------------------
// RMSNorm: one warp per token (128 elems = 32 lanes x float4)
// ---------------------------------------------------------------------------
__global__ void rmsnorm_kernel(const float* __restrict__ x,
                               const float* __restrict__ gw,
                               float* __restrict__ y) {
    int warp = (blockIdx.x * blockDim.x + threadIdx.x) >> 5;
    int lane = threadIdx.x & 31;
    if (warp >= NTOK) return;
    float4 v = reinterpret_cast<const float4*>(x + (size_t)warp * EDIM)[lane];
    float ss = v.x * v.x + v.y * v.y + v.z * v.z + v.w * v.w;
    #pragma unroll
    for (int o = 16; o > 0; o >>= 1) ss += __shfl_xor_sync(0xffffffffu, ss, o);
    float s = rsqrtf(ss * (1.0f / 128.0f) + 1e-6f);
    float4 g4 = reinterpret_cast<const float4*>(gw)[lane];
    float4 o4 = make_float4(v.x * s * g4.x, v.y * s * g4.y, v.z * s * g4.z, v.w * s * g4.w);
    reinterpret_cast<float4*>(y + (size_t)warp * EDIM)[lane] = o4;
}

// ---------------------------------------------------------------------------
// Pack Wq|Wk|Wv -> [128][384]
// ---------------------------------------------------------------------------
__global__ void pack_wqkv(const float* __restrict__ Wq,
                          const float* __restrict__ Wk,
                          const float* __restrict__ Wv) {
    int i = blockIdx.x * blockDim.x + threadIdx.x;
    if (i >= EDIM * 3 * EDIM) return;
    int k = i / 384, n = i % 384;
    float v = (n < 128) ? Wq[k * 128 + n]
            : (n < 256) ? Wk[k * 128 + n - 128]
                        : Wv[k * 128 + n - 256];
    g_Wqkv[i] = v;
}

// ---------------------------------------------------------------------------
// S = sigmoid(q); X = [exp(k)*v, exp(k)]
// ---------------------------------------------------------------------------
__global__ void sx_kernel() {
    int i = blockIdx.x * blockDim.x + threadIdx.x;
    if (i >= NTOK * EDIM) return;
    int t = i >> 7, e = i & 127;
    const float* row = g_qkv + (size_t)t * 384;
    float q = row[e], k = row[128 + e], v = row[256 + e];
    g_S[i] = 1.0f / (1.0f + expf(-q));
    float kw = expf(k);
    g_X[(size_t)t * 256 + e]       = kw * v;
    g_X[(size_t)t * 256 + 128 + e] = kw;
}

// ---------------------------------------------------------------------------
// att = sigmoid(q) * w1/w2
// ---------------------------------------------------------------------------
__global__ void att_kernel() {
    int i = blockIdx.x * blockDim.x + threadIdx.x;
    if (i >= NTOK * EDIM) return;
    int t = i >> 7, e = i & 127;
    float w1 = g_C[(size_t)t * 256 + e];
    float w2 = g_C[(size_t)t * 256 + 128 + e];
    g_att[i] = g_S[i] * (w1 / w2);
}

// ---------------------------------------------------------------------------
// Big GEMM: per batch  C[j,c] = sum_i exp(-coef*dis[i,j]) * X[i,c]
// M=4096(j), K=4096(i), N=256(c). BM=128, BN=256, BK=32, 512 threads,
// double-buffered smem, exp fused into A-tile staging, B via cp.async.
// ---------------------------------------------------------------------------
__global__ __launch_bounds__(512)
void gemm_big_kernel(const float* __restrict__ dis, const float* __restrict__ alphap) {
    extern __shared__ float sm[];
    constexpr int ASTR = 136, BSTR = 264;
    constexpr int ABUF = 32 * ASTR, BBUF = 32 * BSTR;
    float* As = sm;                 // 2 * ABUF
    float* Bs = sm + 2 * ABUF;      // 2 * BBUF

    const int b  = blockIdx.y;
    const int j0 = blockIdx.x * 128;
    const float* Ab = dis + (size_t)b * NSEQ * NSEQ;
    const float* Xb = g_X + (size_t)b * NSEQ * 256;
    float*       Cb = g_C + (size_t)b * NSEQ * 256;
    const float coef = 12.0f * alphap[0];   // alpha * log2(4096)

    const int tid  = threadIdx.x;
    const int lane = tid & 31, warp = tid >> 5;
    const int wm = warp >> 2, wn = warp & 3;       // 4 x 4 warps
    const int g  = lane >> 2, tg = lane & 3;

    const int ar_r0 = tid >> 5;                    // A stage: 2 rows per thread
    const int ar_c  = (tid & 31) << 2;

    float4 ar[2];
    float acc[2][8][4];
    #pragma unroll
    for (int i = 0; i < 2; i++)
        #pragma unroll
        for (int j = 0; j < 8; j++)
            #pragma unroll
            for (int r = 0; r < 4; r++) acc[i][j][r] = 0.0f;

    // -------- prologue: stage tile 0 --------
    {
        #pragma unroll
        for (int i = 0; i < 4; i++) {
            int id = tid + i * 512;
            int r = id >> 6, c = (id & 63) << 2;
            cp16(Bs + r * BSTR + c, Xb + (size_t)r * 256 + c);
        }
        cp_commit();
        #pragma unroll
        for (int i = 0; i < 2; i++) {
            int r = ar_r0 + i * 16;
            ar[i] = *reinterpret_cast<const float4*>(Ab + (size_t)r * NSEQ + j0 + ar_c);
        }
        #pragma unroll
        for (int i = 0; i < 2; i++) {
            int r = ar_r0 + i * 16;
            float* p = As + r * ASTR + ar_c;
            p[0] = tf32r(__expf(-coef * ar[i].x));
            p[1] = tf32r(__expf(-coef * ar[i].y));
            p[2] = tf32r(__expf(-coef * ar[i].z));
            p[3] = tf32r(__expf(-coef * ar[i].w));
        }
        cp_wait0();
        __syncthreads();
    }

    const int KT = NSEQ / 32;
    for (int kt = 0; kt < KT; ++kt) {
        const int buf = kt & 1;
        const bool more = (kt + 1 < KT);
        if (more) {
            const int k0 = (kt + 1) * 32;
            #pragma unroll
            for (int i = 0; i < 4; i++) {
                int id = tid + i * 512;
                int r = id >> 6, c = (id & 63) << 2;
                cp16(Bs + (buf ^ 1) * BBUF + r * BSTR + c, Xb + (size_t)(k0 + r) * 256 + c);
            }
            cp_commit();
            #pragma unroll
            for (int i = 0; i < 2; i++) {
                int r = ar_r0 + i * 16;
                ar[i] = *reinterpret_cast<const float4*>(Ab + (size_t)(k0 + r) * NSEQ + j0 + ar_c);
            }
        }
        const float* A  = As + buf * ABUF;
        const float* Bm = Bs + buf * BBUF;
        #pragma unroll
        for (int ks = 0; ks < 4; ++ks) {
            const int kr = ks * 8 + tg;
            float a[2][4];
            #pragma unroll
            for (int mt = 0; mt < 2; ++mt) {
                int m = wm * 32 + mt * 16 + g;
                a[mt][0] = A[kr * ASTR + m];
                a[mt][1] = A[kr * ASTR + m + 8];
                a[mt][2] = A[(kr + 4) * ASTR + m];
                a[mt][3] = A[(kr + 4) * ASTR + m + 8];
            }
            float bb[8][2];
            #pragma unroll
            for (int nt = 0; nt < 8; ++nt) {
                int n = wn * 64 + nt * 8 + g;
                bb[nt][0] = Bm[kr * BSTR + n];
                bb[nt][1] = Bm[(kr + 4) * BSTR + n];
            }
            #pragma unroll
            for (int mt = 0; mt < 2; ++mt)
                #pragma unroll
                for (int nt = 0; nt < 8; ++nt)
                    mma_tf32(acc[mt][nt], a[mt], bb[nt]);
        }
        if (more) {
            float* Ad = As + (buf ^ 1) * ABUF;
            #pragma unroll
            for (int i = 0; i < 2; i++) {
                int r = ar_r0 + i * 16;
                float* p = Ad + r * ASTR + ar_c;
                p[0] = tf32r(__expf(-coef * ar[i].x));
                p[1] = tf32r(__expf(-coef * ar[i].y));
                p[2] = tf32r(__expf(-coef * ar[i].z));
                p[3] = tf32r(__expf(-coef * ar[i].w));
            }
            cp_wait0();
        }
        __syncthreads();
    }

    // -------- epilogue --------
    #pragma unroll
    for (int mt = 0; mt < 2; ++mt) {
        const int row0 = j0 + wm * 32 + mt * 16 + g;
        #pragma unroll
        for (int nt = 0; nt < 8; ++nt) {
            const int col = wn * 64 + nt * 8 + tg * 2;
            float* p0 = Cb + (size_t)row0 * 256 + col;
            float* p1 = Cb + (size_t)(row0 + 8) * 256 + col;
            p0[0] = acc[mt][nt][0]; p0[1] = acc[mt][nt][1];
            p1[0] = acc[mt][nt][2]; p1[1] = acc[mt][nt][3];
        }
    }
}

// ---------------------------------------------------------------------------
// Generic small GEMM: C[M,N] = A[M,K] @ B[K,N] (+ epilogue)
// BM=128, BN=64, BK=32, 256 threads, single-buffered smem (tf32-rna staged)
// mode 0: store   1: +res   2: relu(+bias)   3: +bias+res
// ---------------------------------------------------------------------------
__global__ __launch_bounds__(256)
void gemm_small_kernel(const float* __restrict__ A, const float* __restrict__ B,
                       float* __restrict__ C, int K, int N, int mode,
                       const float* __restrict__ bias, const float* __restrict__ res) {
    __shared__ float As[128 * 36];
    __shared__ float Bs[32 * 72];
    const int m0 = blockIdx.x * 128;
    const int n0 = blockIdx.y * 64;
    const int tid = threadIdx.x, lane = tid & 31, warp = tid >> 5;
    const int wm = warp >> 1, wn = warp & 1;        // 4 x 2 warps
    const int g = lane >> 2, tg = lane & 3;

    float acc[2][4][4];
    #pragma unroll
    for (int i = 0; i < 2; i++)
        #pragma unroll
        for (int j = 0; j < 4; j++)
            #pragma unroll
            for (int r = 0; r < 4; r++) acc[i][j][r] = 0.0f;

    for (int k0 = 0; k0 < K; k0 += 32) {
        #pragma unroll
        for (int i = 0; i < 4; i++) {
            int id = tid + i * 256;
            int m = id >> 3, c = (id & 7) << 2;
            float4 v = *reinterpret_cast<const float4*>(A + (size_t)(m0 + m) * K + k0 + c);
            float* p = As + m * 36 + c;
            p[0] = tf32r(v.x); p[1] = tf32r(v.y); p[2] = tf32r(v.z); p[3] = tf32r(v.w);
        }
        #pragma unroll
        for (int i = 0; i < 2; i++) {
            int id = tid + i * 256;
            int k = id >> 4, c = (id & 15) << 2;
            float4 v = *reinterpret_cast<const float4*>(B + (size_t)(k0 + k) * N + n0 + c);
            float* p = Bs + k * 72 + c;
            p[0] = tf32r(v.x); p[1] = tf32r(v.y); p[2] = tf32r(v.z); p[3] = tf32r(v.w);
        }
        __syncthreads();
        #pragma unroll
        for (int ks = 0; ks < 4; ++ks) {
            const int kr = ks * 8 + tg;
            float a[2][4];
            #pragma unroll
            for (int mt = 0; mt < 2; ++mt) {
                int m = wm * 32 + mt * 16 + g;
                a[mt][0] = As[m * 36 + kr];
                a[mt][1] = As[(m + 8) * 36 + kr];
                a[mt][2] = As[m * 36 + kr + 4];
                a[mt][3] = As[(m + 8) * 36 + kr + 4];
            }
            float bb[4][2];
            #pragma unroll
            for (int nt = 0; nt < 4; ++nt) {
                int n = wn * 32 + nt * 8 + g;
                bb[nt][0] = Bs[kr * 72 + n];
                bb[nt][1] = Bs[(kr + 4) * 72 + n];
            }
            #pragma unroll
            for (int mt = 0; mt < 2; ++mt)
                #pragma unroll
                for (int nt = 0; nt < 4; ++nt)
                    mma_tf32(acc[mt][nt], a[mt], bb[nt]);
        }
        __syncthreads();
    }

    #pragma unroll
    for (int mt = 0; mt < 2; ++mt) {
        const int row0 = m0 + wm * 32 + mt * 16 + g;
        #pragma unroll
        for (int nt = 0; nt < 4; ++nt) {
            const int col = n0 + wn * 32 + nt * 8 + tg * 2;
            #pragma unroll
            for (int h = 0; h < 2; ++h) {
                const int row = row0 + h * 8;
                float v0 = acc[mt][nt][h * 2 + 0];
                float v1 = acc[mt][nt][h * 2 + 1];
                if (mode == 1) {
                    v0 += res[(size_t)row * N + col];
                    v1 += res[(size_t)row * N + col + 1];
                } else if (mode == 2) {
                    v0 = fmaxf(v0 + bias[col], 0.0f);
                    v1 = fmaxf(v1 + bias[col + 1], 0.0f);
                } else if (mode == 3) {
                    v0 += bias[col]     + res[(size_t)row * N + col];
                    v1 += bias[col + 1] + res[(size_t)row * N + col + 1];
                }
                C[(size_t)row * N + col]     = v0;
                C[(size_t)row * N + col + 1] = v1;
            }
        }
    }
}

// ---------------------------------------------------------------------------
// Launch
// ---------------------------------------------------------------------------
extern "C" void kernel_launch(void* const* d_in, const int* in_sizes, int n_in,
                              void* d_out, int out_size) {
    const float* x     = (const float*)d_in[0];
    const float* dis   = (const float*)d_in[1];
    const float* g_in  = (const float*)d_in[2];
    const float* g_po  = (const float*)d_in[3];
    const float* Wq    = (const float*)d_in[4];
    const float* Wk    = (const float*)d_in[5];
    const float* Wv    = (const float*)d_in[6];
    const float* alpha = (const float*)d_in[7];
    const float* Wo    = (const float*)d_in[8];
    const float* W1    = (const float*)d_in[9];
    const float* b1    = (const float*)d_in[10];
    const float* W2    = (const float*)d_in[11];
    const float* b2    = (const float*)d_in[12];
    float* out = (float*)d_out;

    float *p_h, *p_qkv, *p_att, *p_out1, *p_h2, *p_t, *p_wqkv;
    cudaGetSymbolAddress((void**)&p_h,    g_h);
    cudaGetSymbolAddress((void**)&p_qkv,  g_qkv);
    cudaGetSymbolAddress((void**)&p_att,  g_att);
    cudaGetSymbolAddress((void**)&p_out1, g_out1);
    cudaGetSymbolAddress((void**)&p_h2,   g_h2);
    cudaGetSymbolAddress((void**)&p_t,    g_t);
    cudaGetSymbolAddress((void**)&p_wqkv, g_Wqkv);

    cudaFuncSetAttribute(gemm_big_kernel,
                         cudaFuncAttributeMaxDynamicSharedMemorySize, 102400);

    const int ew_blocks = (NTOK * EDIM + 255) / 256;

    // 1) pack QKV weights
    pack_wqkv<<<(EDIM * 3 * EDIM + 255) / 256, 256>>>(Wq, Wk, Wv);
    // 2) h = rmsnorm(x, g_in)
    rmsnorm_kernel<<<NTOK / 8, 256>>>(x, g_in, p_h);
    // 3) qkv = h @ [Wq|Wk|Wv]
    gemm_small_kernel<<<dim3(NTOK / 128, 6), 256>>>(p_h, p_wqkv, p_qkv,
                                                    128, 384, 0, nullptr, nullptr);
    // 4) S, X
    sx_kernel<<<ew_blocks, 256>>>();
    // 5) big GEMM: C = exp(-coef*dis)^T @ X  (per batch)
    gemm_big_kernel<<<dim3(NSEQ / 128, NB), 512, 102400>>>(dis, alpha);
    // 6) att = S * w1/w2
    att_kernel<<<ew_blocks, 256>>>();
    // 7) out1 = x + att @ Wo
    gemm_small_kernel<<<dim3(NTOK / 128, 2), 256>>>(p_att, Wo, p_out1,
                                                    128, 128, 1, nullptr, x);
    // 8) h2 = rmsnorm(out1, g_post)
    rmsnorm_kernel<<<NTOK / 8, 256>>>(p_out1, g_po, p_h2);
    // 9) t = relu(h2 @ W1 + b1)
    gemm_small_kernel<<<dim3(NTOK / 128, 8), 256>>>(p_h2, W1, p_t,
                                                    128, 512, 2, b1, nullptr);
    // 10) out = out1 + t @ W2 + b2
    gemm_small_kernel<<<dim3(NTOK / 128, 2), 256>>>(p_t, W2, out,
                                                    512, 128, 3, b2, p_out1);
}

// round 4
// speedup vs baseline: 1.1976x; 1.1973x over previous
#include <cuda_runtime.h>
#include <cuda_fp16.h>
#include <cstdint>
#include <cstddef>

#define NB     4
#define NSEQ   4096
#define EDIM   128
#define FFD    512
#define NTOK   (NB * NSEQ)

// ---------------- scratch ----------------
__device__ float g_h   [NTOK * EDIM];
__device__ float g_qkv [NTOK * 3 * EDIM];
__device__ float g_S   [NTOK * EDIM];
__device__ float g_X   [NTOK * 2 * EDIM];   // [t][256]: col 2e=exp(k)*v, 2e+1=exp(k)
__device__ float g_att [NTOK * EDIM];
__device__ float g_out1[NTOK * EDIM];
__device__ float g_h2  [NTOK * EDIM];
__device__ float g_t   [NTOK * FFD];
__device__ float g_Wqkv[EDIM * 3 * EDIM];

// ---------------- helpers ----------------
__device__ __forceinline__ float tf32r(float x) {
    uint32_t u;
    asm("cvt.rna.tf32.f32 %0, %1;" : "=r"(u) : "f"(x));
    return __uint_as_float(u);
}
__device__ __forceinline__ void mma_tf32(float* c, const float* a, const float* b) {
    asm volatile(
        "mma.sync.aligned.m16n8k8.row.col.f32.tf32.tf32.f32 "
        "{%0,%1,%2,%3}, {%4,%5,%6,%7}, {%8,%9}, {%0,%1,%2,%3};\n"
        : "+f"(c[0]), "+f"(c[1]), "+f"(c[2]), "+f"(c[3])
        : "r"(__float_as_uint(a[0])), "r"(__float_as_uint(a[1])),
          "r"(__float_as_uint(a[2])), "r"(__float_as_uint(a[3])),
          "r"(__float_as_uint(b[0])), "r"(__float_as_uint(b[1])));
}
__device__ __forceinline__ void mma_f16(float* c, const uint32_t* a, const uint32_t* b) {
    asm volatile(
        "mma.sync.aligned.m16n8k16.row.col.f32.f16.f16.f32 "
        "{%0,%1,%2,%3}, {%4,%5,%6,%7}, {%8,%9}, {%0,%1,%2,%3};\n"
        : "+f"(c[0]), "+f"(c[1]), "+f"(c[2]), "+f"(c[3])
        : "r"(a[0]), "r"(a[1]), "r"(a[2]), "r"(a[3]), "r"(b[0]), "r"(b[1]));
}

// ---------------- rmsnorm ----------------
__global__ void rmsnorm_kernel(const float* __restrict__ x,
                               const float* __restrict__ gw,
                               float* __restrict__ y) {
    int warp = (blockIdx.x * blockDim.x + threadIdx.x) >> 5;
    int lane = threadIdx.x & 31;
    if (warp >= NTOK) return;
    float4 v = reinterpret_cast<const float4*>(x + (size_t)warp * EDIM)[lane];
    float ss = v.x * v.x + v.y * v.y + v.z * v.z + v.w * v.w;
    #pragma unroll
    for (int o = 16; o > 0; o >>= 1) ss += __shfl_xor_sync(0xffffffffu, ss, o);
    float s = rsqrtf(ss * (1.0f / 128.0f) + 1e-6f);
    float4 g4 = reinterpret_cast<const float4*>(gw)[lane];
    float4 o4 = make_float4(v.x * s * g4.x, v.y * s * g4.y, v.z * s * g4.z, v.w * s * g4.w);
    reinterpret_cast<float4*>(y + (size_t)warp * EDIM)[lane] = o4;
}

// ---------------- pack Wq|Wk|Wv ----------------
__global__ void pack_wqkv(const float* __restrict__ Wq,
                          const float* __restrict__ Wk,
                          const float* __restrict__ Wv) {
    int i = blockIdx.x * blockDim.x + threadIdx.x;
    if (i >= EDIM * 3 * EDIM) return;
    int k = i / 384, n = i % 384;
    float v = (n < 128) ? Wq[k * 128 + n]
            : (n < 256) ? Wk[k * 128 + n - 128]
                        : Wv[k * 128 + n - 256];
    g_Wqkv[i] = v;
}

// ---------------- S = sigmoid(q); X interleaved ----------------
__global__ void sx_kernel(int off) {
    int i = off + blockIdx.x * blockDim.x + threadIdx.x;
    if (i >= NTOK * EDIM) return;
    int t = i >> 7, e = i & 127;
    const float* row = g_qkv + (size_t)t * 384;
    float q = row[e], k = row[128 + e], v = row[256 + e];
    g_S[i] = 1.0f / (1.0f + expf(-q));
    float kw = expf(k);
    g_X[(size_t)t * 256 + 2 * e]     = kw * v;
    g_X[(size_t)t * 256 + 2 * e + 1] = kw;
}

// ---------------------------------------------------------------------------
// Big GEMM (fp16 mma.sync m16n8k16), per batch:
//   D[j,n] = sum_i exp(-coef*dis[i,j]) * X[i,n],  M=128/blk, N=256, BK=32.
// smem: A [m][k] and B [n][k], 36-half padded rows, double buffered.
// Fused epilogue: att = sigmoid(q) * w1/w2 (w1,w2 = adjacent cols).
// ---------------------------------------------------------------------------
#define BIG_SMEM 55296
__global__ __launch_bounds__(512, 1)
void big_kernel(const float* __restrict__ dis, const float* __restrict__ alphap) {
    extern __shared__ __half smh[];
    __half* A0 = smh;            // 2 x 128*36
    __half* B0 = smh + 9216;     // 2 x 256*36

    const int tid = threadIdx.x, lane = tid & 31, warp = tid >> 5;
    const int wm = warp >> 2, wn = warp & 3;     // 4 x 4 warps
    const int g = lane >> 2, tg = lane & 3;
    const int b = blockIdx.y, j0 = blockIdx.x * 128;
    const float coef = 12.0f * alphap[0];
    const float* Ag = dis + (size_t)b * NSEQ * NSEQ;
    const float* Xg = g_X + (size_t)b * NSEQ * 256;

    const int am = tid & 127, ar4 = (tid >> 7) << 2;   // A: col m, 4 k-rows
    const int bc = tid & 255, br4 = (tid >> 8) << 2;   // B: col n, 4 k-rows

    float ra[2][4], rb[4][4];
    float acc[2][8][4];
    #pragma unroll
    for (int i = 0; i < 2; i++)
        #pragma unroll
        for (int j = 0; j < 8; j++)
            #pragma unroll
            for (int r = 0; r < 4; r++) acc[i][j][r] = 0.0f;

    auto ldA = [&](int k0) {
        #pragma unroll
        for (int it = 0; it < 2; ++it) {
            const float* p = Ag + (size_t)(k0 + it * 16 + ar4) * NSEQ + j0 + am;
            ra[it][0] = p[0]; ra[it][1] = p[NSEQ];
            ra[it][2] = p[2 * NSEQ]; ra[it][3] = p[3 * NSEQ];
        }
    };
    auto ldB = [&](int k0) {
        #pragma unroll
        for (int it = 0; it < 4; ++it) {
            const float* p = Xg + (size_t)(k0 + it * 8 + br4) * 256 + bc;
            rb[it][0] = p[0]; rb[it][1] = p[256];
            rb[it][2] = p[512]; rb[it][3] = p[768];
        }
    };
    auto stA = [&](int buf) {
        __half* base = A0 + buf * 4608 + am * 36;
        #pragma unroll
        for (int it = 0; it < 2; ++it) {
            __half2 h01 = __floats2half2_rn(__expf(-coef * ra[it][0]),
                                            __expf(-coef * ra[it][1]));
            __half2 h23 = __floats2half2_rn(__expf(-coef * ra[it][2]),
                                            __expf(-coef * ra[it][3]));
            uint2 u;
            u.x = *reinterpret_cast<uint32_t*>(&h01);
            u.y = *reinterpret_cast<uint32_t*>(&h23);
            *reinterpret_cast<uint2*>(base + it * 16 + ar4) = u;
        }
    };
    auto stB = [&](int buf) {
        __half* base = B0 + buf * 9216 + bc * 36;
        #pragma unroll
        for (int it = 0; it < 4; ++it) {
            __half2 h01 = __floats2half2_rn(rb[it][0], rb[it][1]);
            __half2 h23 = __floats2half2_rn(rb[it][2], rb[it][3]);
            uint2 u;
            u.x = *reinterpret_cast<uint32_t*>(&h01);
            u.y = *reinterpret_cast<uint32_t*>(&h23);
            *reinterpret_cast<uint2*>(base + it * 8 + br4) = u;
        }
    };

    // prologue
    ldA(0); ldB(0); stA(0); stB(0);
    __syncthreads();

    for (int kt = 0; kt < 128; ++kt) {
        const int buf = kt & 1;
        const bool more = (kt + 1 < 128);
        if (more) { ldA((kt + 1) * 32); ldB((kt + 1) * 32); }

        const __half* A = A0 + buf * 4608;
        const __half* B = B0 + buf * 9216;
        #pragma unroll
        for (int ks = 0; ks < 2; ++ks) {
            const int kb = ks * 16 + tg * 2;
            uint32_t a[2][4];
            #pragma unroll
            for (int mt = 0; mt < 2; ++mt) {
                const int m = wm * 32 + mt * 16 + g;
                a[mt][0] = *reinterpret_cast<const uint32_t*>(A + m * 36 + kb);
                a[mt][1] = *reinterpret_cast<const uint32_t*>(A + (m + 8) * 36 + kb);
                a[mt][2] = *reinterpret_cast<const uint32_t*>(A + m * 36 + kb + 8);
                a[mt][3] = *reinterpret_cast<const uint32_t*>(A + (m + 8) * 36 + kb + 8);
            }
            #pragma unroll
            for (int nt = 0; nt < 8; ++nt) {
                const int n = wn * 64 + nt * 8 + g;
                uint32_t bb[2];
                bb[0] = *reinterpret_cast<const uint32_t*>(B + n * 36 + kb);
                bb[1] = *reinterpret_cast<const uint32_t*>(B + n * 36 + kb + 8);
                mma_f16(acc[0][nt], a[0], bb);
                mma_f16(acc[1][nt], a[1], bb);
            }
        }
        if (more) { stA(buf ^ 1); stB(buf ^ 1); }
        __syncthreads();
    }

    // fused epilogue: att = S * w1/w2
    const size_t rowbase = (size_t)b * NSEQ + j0;
    #pragma unroll
    for (int mt = 0; mt < 2; ++mt) {
        const int r0 = wm * 32 + mt * 16 + g;
        #pragma unroll
        for (int nt = 0; nt < 8; ++nt) {
            const int e = wn * 32 + nt * 4 + tg;
            const size_t i0 = (rowbase + r0) * 128 + e;
            const size_t i1 = (rowbase + r0 + 8) * 128 + e;
            g_att[i0] = g_S[i0] * __fdividef(acc[mt][nt][0], acc[mt][nt][1]);
            g_att[i1] = g_S[i1] * __fdividef(acc[mt][nt][2], acc[mt][nt][3]);
        }
    }
}

// ---------------- small GEMM (tf32 mma) ----------------
// mode 0: store  1: +res  2: relu(+bias)  3: +bias+res
__global__ __launch_bounds__(256)
void gemm_small_kernel(const float* __restrict__ A, const float* __restrict__ B,
                       float* __restrict__ C, int K, int N, int mode,
                       const float* __restrict__ bias, const float* __restrict__ res) {
    __shared__ float As[128 * 36];
    __shared__ float Bs[32 * 72];
    const int m0 = blockIdx.x * 128;
    const int n0 = blockIdx.y * 64;
    const int tid = threadIdx.x, lane = tid & 31, warp = tid >> 5;
    const int wm = warp >> 1, wn = warp & 1;
    const int g = lane >> 2, tg = lane & 3;

    float acc[2][4][4];
    #pragma unroll
    for (int i = 0; i < 2; i++)
        #pragma unroll
        for (int j = 0; j < 4; j++)
            #pragma unroll
            for (int r = 0; r < 4; r++) acc[i][j][r] = 0.0f;

    for (int k0 = 0; k0 < K; k0 += 32) {
        #pragma unroll
        for (int i = 0; i < 4; i++) {
            int id = tid + i * 256;
            int m = id >> 3, c = (id & 7) << 2;
            float4 v = *reinterpret_cast<const float4*>(A + (size_t)(m0 + m) * K + k0 + c);
            float* p = As + m * 36 + c;
            p[0] = tf32r(v.x); p[1] = tf32r(v.y); p[2] = tf32r(v.z); p[3] = tf32r(v.w);
        }
        #pragma unroll
        for (int i = 0; i < 2; i++) {
            int id = tid + i * 256;
            int k = id >> 4, c = (id & 15) << 2;
            float4 v = *reinterpret_cast<const float4*>(B + (size_t)(k0 + k) * N + n0 + c);
            float* p = Bs + k * 72 + c;
            p[0] = tf32r(v.x); p[1] = tf32r(v.y); p[2] = tf32r(v.z); p[3] = tf32r(v.w);
        }
        __syncthreads();
        #pragma unroll
        for (int ks = 0; ks < 4; ++ks) {
            const int kr = ks * 8 + tg;
            float a[2][4];
            #pragma unroll
            for (int mt = 0; mt < 2; ++mt) {
                int m = wm * 32 + mt * 16 + g;
                a[mt][0] = As[m * 36 + kr];
                a[mt][1] = As[(m + 8) * 36 + kr];
                a[mt][2] = As[m * 36 + kr + 4];
                a[mt][3] = As[(m + 8) * 36 + kr + 4];
            }
            float bb[4][2];
            #pragma unroll
            for (int nt = 0; nt < 4; ++nt) {
                int n = wn * 32 + nt * 8 + g;
                bb[nt][0] = Bs[kr * 72 + n];
                bb[nt][1] = Bs[(kr + 4) * 72 + n];
            }
            #pragma unroll
            for (int mt = 0; mt < 2; ++mt)
                #pragma unroll
                for (int nt = 0; nt < 4; ++nt)
                    mma_tf32(acc[mt][nt], a[mt], bb[nt]);
        }
        __syncthreads();
    }

    #pragma unroll
    for (int mt = 0; mt < 2; ++mt) {
        const int row0 = m0 + wm * 32 + mt * 16 + g;
        #pragma unroll
        for (int nt = 0; nt < 4; ++nt) {
            const int col = n0 + wn * 32 + nt * 8 + tg * 2;
            #pragma unroll
            for (int h = 0; h < 2; ++h) {
                const int row = row0 + h * 8;
                float v0 = acc[mt][nt][h * 2 + 0];
                float v1 = acc[mt][nt][h * 2 + 1];
                if (mode == 1) {
                    v0 += res[(size_t)row * N + col];
                    v1 += res[(size_t)row * N + col + 1];
                } else if (mode == 2) {
                    v0 = fmaxf(v0 + bias[col], 0.0f);
                    v1 = fmaxf(v1 + bias[col + 1], 0.0f);
                } else if (mode == 3) {
                    v0 += bias[col]     + res[(size_t)row * N + col];
                    v1 += bias[col + 1] + res[(size_t)row * N + col + 1];
                }
                C[(size_t)row * N + col]     = v0;
                C[(size_t)row * N + col + 1] = v1;
            }
        }
    }
}

// ---------------- launch ----------------
extern "C" void kernel_launch(void* const* d_in, const int* in_sizes, int n_in,
                              void* d_out, int out_size) {
    const float* x     = (const float*)d_in[0];
    const float* dis   = (const float*)d_in[1];
    const float* g_in  = (const float*)d_in[2];
    const float* g_po  = (const float*)d_in[3];
    const float* Wq    = (const float*)d_in[4];
    const float* Wk    = (const float*)d_in[5];
    const float* Wv    = (const float*)d_in[6];
    const float* alpha = (const float*)d_in[7];
    const float* Wo    = (const float*)d_in[8];
    const float* W1    = (const float*)d_in[9];
    const float* b1    = (const float*)d_in[10];
    const float* W2    = (const float*)d_in[11];
    const float* b2    = (const float*)d_in[12];
    float* out = (float*)d_out;

    float *p_h, *p_qkv, *p_att, *p_out1, *p_h2, *p_t, *p_wqkv;
    cudaGetSymbolAddress((void**)&p_h,    g_h);
    cudaGetSymbolAddress((void**)&p_qkv,  g_qkv);
    cudaGetSymbolAddress((void**)&p_att,  g_att);
    cudaGetSymbolAddress((void**)&p_out1, g_out1);
    cudaGetSymbolAddress((void**)&p_h2,   g_h2);
    cudaGetSymbolAddress((void**)&p_t,    g_t);
    cudaGetSymbolAddress((void**)&p_wqkv, g_Wqkv);

    cudaFuncSetAttribute(big_kernel,
                         cudaFuncAttributeMaxDynamicSharedMemorySize, BIG_SMEM);

    const int half_elems = NTOK * EDIM / 2;

    pack_wqkv<<<(EDIM * 3 * EDIM + 255) / 256, 256>>>(Wq, Wk, Wv);
    rmsnorm_kernel<<<NTOK / 8, 256>>>(x, g_in, p_h);
    gemm_small_kernel<<<dim3(NTOK / 128, 6), 256>>>(p_h, p_wqkv, p_qkv,
                                                    128, 384, 0, nullptr, nullptr);
    sx_kernel<<<half_elems / 256, 256>>>(0);
    sx_kernel<<<half_elems / 256, 256>>>(half_elems);
    // launch #6 -> ncu -s 5 -c 1 captures this one
    big_kernel<<<dim3(NSEQ / 128, NB), 512, BIG_SMEM>>>(dis, alpha);
    gemm_small_kernel<<<dim3(NTOK / 128, 2), 256>>>(p_att, Wo, p_out1,
                                                    128, 128, 1, nullptr, x);
    rmsnorm_kernel<<<NTOK / 8, 256>>>(p_out1, g_po, p_h2);
    gemm_small_kernel<<<dim3(NTOK / 128, 8), 256>>>(p_h2, W1, p_t,
                                                    128, 512, 2, b1, nullptr);
    gemm_small_kernel<<<dim3(NTOK / 128, 2), 256>>>(p_t, W2, out,
                                                    512, 128, 3, b2, p_out1);
}

// round 5
// speedup vs baseline: 1.3710x; 1.1448x over previous
#include <cuda_runtime.h>
#include <cuda_fp16.h>
#include <cstdint>
#include <cstddef>

#define NB     4
#define NSEQ   4096
#define EDIM   128
#define FFD    512
#define NTOK   (NB * NSEQ)

// ---------------- scratch ----------------
__device__ float  g_h   [NTOK * EDIM];
__device__ float  g_S   [NTOK * EDIM];
__device__ __half g_Xh  [NTOK * 256];     // [t][256]: 2e=exp(k)*v, 2e+1=exp(k)
__device__ float  g_att [NTOK * EDIM];
__device__ float  g_out1[NTOK * EDIM];
__device__ float  g_h2  [NTOK * EDIM];
__device__ float  g_t   [NTOK * FFD];

// ---------------- helpers ----------------
__device__ __forceinline__ float tf32r(float x) {
    uint32_t u;
    asm("cvt.rna.tf32.f32 %0, %1;" : "=r"(u) : "f"(x));
    return __uint_as_float(u);
}
__device__ __forceinline__ void mma_tf32(float* c, const float* a, const float* b) {
    asm volatile(
        "mma.sync.aligned.m16n8k8.row.col.f32.tf32.tf32.f32 "
        "{%0,%1,%2,%3}, {%4,%5,%6,%7}, {%8,%9}, {%0,%1,%2,%3};\n"
        : "+f"(c[0]), "+f"(c[1]), "+f"(c[2]), "+f"(c[3])
        : "r"(__float_as_uint(a[0])), "r"(__float_as_uint(a[1])),
          "r"(__float_as_uint(a[2])), "r"(__float_as_uint(a[3])),
          "r"(__float_as_uint(b[0])), "r"(__float_as_uint(b[1])));
}
__device__ __forceinline__ void mma_f16(float* c, const uint32_t* a, const uint32_t* b) {
    asm volatile(
        "mma.sync.aligned.m16n8k16.row.col.f32.f16.f16.f32 "
        "{%0,%1,%2,%3}, {%4,%5,%6,%7}, {%8,%9}, {%0,%1,%2,%3};\n"
        : "+f"(c[0]), "+f"(c[1]), "+f"(c[2]), "+f"(c[3])
        : "r"(a[0]), "r"(a[1]), "r"(a[2]), "r"(a[3]), "r"(b[0]), "r"(b[1]));
}
__device__ __forceinline__ void cp16(void* s, const void* gp) {
    uint32_t sa = (uint32_t)__cvta_generic_to_shared(s);
    asm volatile("cp.async.cg.shared.global [%0], [%1], 16;\n" :: "r"(sa), "l"(gp));
}
__device__ __forceinline__ void cp_commit() {
    asm volatile("cp.async.commit_group;\n" ::: "memory");
}
__device__ __forceinline__ void cp_wait0() {
    asm volatile("cp.async.wait_group 0;\n" ::: "memory");
}
__device__ __forceinline__ void ldmx4t(uint32_t& r0, uint32_t& r1, uint32_t& r2,
                                       uint32_t& r3, uint32_t addr) {
    asm volatile("ldmatrix.sync.aligned.m8n8.x4.trans.shared.b16 {%0,%1,%2,%3}, [%4];"
                 : "=r"(r0), "=r"(r1), "=r"(r2), "=r"(r3) : "r"(addr));
}
__device__ __forceinline__ uint32_t smem_u32(const void* p) {
    return (uint32_t)__cvta_generic_to_shared(p);
}

// ---------------- rmsnorm (token-offset variant for launch splitting) -------
__global__ void rmsnorm_kernel(const float* __restrict__ x,
                               const float* __restrict__ gw,
                               float* __restrict__ y, int tok0) {
    int warp = tok0 + ((blockIdx.x * blockDim.x + threadIdx.x) >> 5);
    int lane = threadIdx.x & 31;
    if (warp >= NTOK) return;
    float4 v = reinterpret_cast<const float4*>(x + (size_t)warp * EDIM)[lane];
    float ss = v.x * v.x + v.y * v.y + v.z * v.z + v.w * v.w;
    #pragma unroll
    for (int o = 16; o > 0; o >>= 1) ss += __shfl_xor_sync(0xffffffffu, ss, o);
    float s = rsqrtf(ss * (1.0f / 128.0f) + 1e-6f);
    float4 g4 = reinterpret_cast<const float4*>(gw)[lane];
    float4 o4 = make_float4(v.x * s * g4.x, v.y * s * g4.y, v.z * s * g4.z, v.w * s * g4.w);
    reinterpret_cast<float4*>(y + (size_t)warp * EDIM)[lane] = o4;
}

// ---------------------------------------------------------------------------
// Fused QKV GEMM: one block = 128 tokens x 32 cols of q,k,v simultaneously.
// Epilogue: g_S = sigmoid(q); g_Xh[t][2e,2e+1] = half(exp(k)*v), half(exp(k)).
// ---------------------------------------------------------------------------
__global__ __launch_bounds__(256)
void qkv_kernel(const float* __restrict__ h, const float* __restrict__ Wq,
                const float* __restrict__ Wk, const float* __restrict__ Wv) {
    __shared__ float As[128 * 36];
    __shared__ float Bs[3][32 * 36];
    const int m0 = blockIdx.x * 128;
    const int j0 = blockIdx.y * 32;
    const int tid = threadIdx.x, lane = tid & 31, warp = tid >> 5;
    const int wm = warp >> 1, wn = warp & 1;    // 4 x 2 warps, 32m x 16n each
    const int g = lane >> 2, tg = lane & 3;

    float acc[3][2][2][4];
    #pragma unroll
    for (int w = 0; w < 3; w++)
        #pragma unroll
        for (int i = 0; i < 2; i++)
            #pragma unroll
            for (int j = 0; j < 2; j++)
                #pragma unroll
                for (int r = 0; r < 4; r++) acc[w][i][j][r] = 0.0f;

    const float* Wp[3] = {Wq, Wk, Wv};

    for (int k0 = 0; k0 < 128; k0 += 32) {
        #pragma unroll
        for (int i = 0; i < 4; i++) {
            int id = tid + i * 256;
            int m = id >> 3, c = (id & 7) << 2;
            float4 v = *reinterpret_cast<const float4*>(h + (size_t)(m0 + m) * 128 + k0 + c);
            float* p = As + m * 36 + c;
            p[0] = tf32r(v.x); p[1] = tf32r(v.y); p[2] = tf32r(v.z); p[3] = tf32r(v.w);
        }
        {
            int k = tid >> 3, c = (tid & 7) << 2;
            #pragma unroll
            for (int w = 0; w < 3; w++) {
                float4 v = *reinterpret_cast<const float4*>(Wp[w] + (size_t)(k0 + k) * 128 + j0 + c);
                float* p = Bs[w] + k * 36 + c;
                p[0] = tf32r(v.x); p[1] = tf32r(v.y); p[2] = tf32r(v.z); p[3] = tf32r(v.w);
            }
        }
        __syncthreads();
        #pragma unroll
        for (int ks = 0; ks < 4; ++ks) {
            const int kr = ks * 8 + tg;
            float a[2][4];
            #pragma unroll
            for (int mt = 0; mt < 2; ++mt) {
                int m = wm * 32 + mt * 16 + g;
                a[mt][0] = As[m * 36 + kr];
                a[mt][1] = As[(m + 8) * 36 + kr];
                a[mt][2] = As[m * 36 + kr + 4];
                a[mt][3] = As[(m + 8) * 36 + kr + 4];
            }
            #pragma unroll
            for (int w = 0; w < 3; w++) {
                #pragma unroll
                for (int nt = 0; nt < 2; ++nt) {
                    int n = wn * 16 + nt * 8 + g;
                    float bb[2];
                    bb[0] = Bs[w][kr * 36 + n];
                    bb[1] = Bs[w][(kr + 4) * 36 + n];
                    mma_tf32(acc[w][0][nt], a[0], bb);
                    mma_tf32(acc[w][1][nt], a[1], bb);
                }
            }
        }
        __syncthreads();
    }

    // epilogue
    #pragma unroll
    for (int mt = 0; mt < 2; ++mt) {
        #pragma unroll
        for (int nt = 0; nt < 2; ++nt) {
            const int col = j0 + wn * 16 + nt * 8 + tg * 2;
            #pragma unroll
            for (int hh = 0; hh < 2; ++hh) {
                const int row = m0 + wm * 32 + mt * 16 + g + hh * 8;
                float q0 = acc[0][mt][nt][hh * 2], q1 = acc[0][mt][nt][hh * 2 + 1];
                float k0v = acc[1][mt][nt][hh * 2], k1v = acc[1][mt][nt][hh * 2 + 1];
                float v0 = acc[2][mt][nt][hh * 2], v1 = acc[2][mt][nt][hh * 2 + 1];
                float2 s2 = make_float2(1.0f / (1.0f + expf(-q0)),
                                        1.0f / (1.0f + expf(-q1)));
                *reinterpret_cast<float2*>(g_S + (size_t)row * 128 + col) = s2;
                float kw0 = expf(k0v), kw1 = expf(k1v);
                __half2 h0 = __floats2half2_rn(kw0 * v0, kw0);
                __half2 h1 = __floats2half2_rn(kw1 * v1, kw1);
                uint2 u;
                u.x = *reinterpret_cast<uint32_t*>(&h0);
                u.y = *reinterpret_cast<uint32_t*>(&h1);
                *reinterpret_cast<uint2*>(g_Xh + (size_t)row * 256 + 2 * col) = u;
            }
        }
    }
}

// ---------------------------------------------------------------------------
// Big GEMM (fp16 m16n8k16), per batch: D[j,n] = sum_i exp(-coef*dis[i,j])*Xh[i,n]
// M=128/blk, N=256, BK=32. A: reg-transposed exp() into [m][36] half smem.
// B: cp.async half [k][264] rows, fragments via ldmatrix.x4.trans.
// Fused epilogue: att = sigmoid(q) * w1/w2.
// ---------------------------------------------------------------------------
#define AH_STR 36
#define AH_BUF 4608            // 128*36 halfs
#define BH_STR 264
#define BH_BUF 8448            // 32*264 halfs
#define BH_OFF 9216            // halfs (after 2 A buffers)
#define BIG_SMEM 52224         // (9216 + 16896) * 2 bytes

__global__ __launch_bounds__(512, 1)
void big_kernel(const float* __restrict__ dis, const float* __restrict__ alphap) {
    extern __shared__ __half smh[];
    __half* Ah = smh;
    __half* Bh = smh + BH_OFF;
    const uint32_t smb = smem_u32(smh);

    const int tid = threadIdx.x, lane = tid & 31, warp = tid >> 5;
    const int wm = warp >> 2, wn = warp & 3;     // 4 x 4 warps: 32m x 64n
    const int g = lane >> 2, tg = lane & 3;
    const int b = blockIdx.y, j0 = blockIdx.x * 128;
    const float coef = 12.0f * alphap[0];
    const float* Ag = dis + (size_t)b * NSEQ * NSEQ;
    const __half* Xg = g_Xh + (size_t)b * NSEQ * 256;

    const int am = tid & 127, ar4 = (tid >> 7) << 2;   // A: col m, 4 k-rows

    // per-thread ldmatrix base offset (halfs, within a B buffer)
    const uint32_t lm_half = (uint32_t)((lane & 15) * BH_STR + wn * 64 + ((lane >> 4) << 3));

    float ra[2][4];
    float acc[2][8][4];
    #pragma unroll
    for (int i = 0; i < 2; i++)
        #pragma unroll
        for (int j = 0; j < 8; j++)
            #pragma unroll
            for (int r = 0; r < 4; r++) acc[i][j][r] = 0.0f;

    auto ldA = [&](int k0) {
        #pragma unroll
        for (int it = 0; it < 2; ++it) {
            const float* p = Ag + (size_t)(k0 + it * 16 + ar4) * NSEQ + j0 + am;
            ra[it][0] = p[0]; ra[it][1] = p[NSEQ];
            ra[it][2] = p[2 * NSEQ]; ra[it][3] = p[3 * NSEQ];
        }
    };
    auto stA = [&](int buf) {
        __half* base = Ah + buf * AH_BUF + am * AH_STR;
        #pragma unroll
        for (int it = 0; it < 2; ++it) {
            __half2 h01 = __floats2half2_rn(__expf(-coef * ra[it][0]),
                                            __expf(-coef * ra[it][1]));
            __half2 h23 = __floats2half2_rn(__expf(-coef * ra[it][2]),
                                            __expf(-coef * ra[it][3]));
            uint2 u;
            u.x = *reinterpret_cast<uint32_t*>(&h01);
            u.y = *reinterpret_cast<uint32_t*>(&h23);
            *reinterpret_cast<uint2*>(base + it * 16 + ar4) = u;
        }
    };
    auto cpB = [&](int buf, int k0) {
        #pragma unroll
        for (int it = 0; it < 2; ++it) {
            int ch = tid + it * 512;
            int row = ch >> 5, cc = (ch & 31) << 3;
            cp16(Bh + buf * BH_BUF + row * BH_STR + cc,
                 Xg + (size_t)(k0 + row) * 256 + cc);
        }
    };

    // prologue
    cpB(0, 0);
    cp_commit();
    ldA(0);
    stA(0);
    cp_wait0();
    __syncthreads();

    for (int kt = 0; kt < 128; ++kt) {
        const int buf = kt & 1;
        const bool more = (kt + 1 < 128);
        if (more) {
            cpB(buf ^ 1, (kt + 1) * 32);
            cp_commit();
            ldA((kt + 1) * 32);
        }

        const __half* A = Ah + buf * AH_BUF;
        const uint32_t bbase = smb + 2u * (BH_OFF + buf * BH_BUF + lm_half);
        #pragma unroll
        for (int ks = 0; ks < 2; ++ks) {
            const int kb = ks * 16;
            const int kbt = kb + tg * 2;
            uint32_t a[2][4];
            #pragma unroll
            for (int mt = 0; mt < 2; ++mt) {
                const int m = wm * 32 + mt * 16 + g;
                a[mt][0] = *reinterpret_cast<const uint32_t*>(A + m * AH_STR + kbt);
                a[mt][1] = *reinterpret_cast<const uint32_t*>(A + (m + 8) * AH_STR + kbt);
                a[mt][2] = *reinterpret_cast<const uint32_t*>(A + m * AH_STR + kbt + 8);
                a[mt][3] = *reinterpret_cast<const uint32_t*>(A + (m + 8) * AH_STR + kbt + 8);
            }
            #pragma unroll
            for (int np = 0; np < 4; ++np) {
                uint32_t r0, r1, r2, r3;
                ldmx4t(r0, r1, r2, r3, bbase + 2u * (kb * BH_STR + np * 16));
                uint32_t b0[2] = {r0, r1}, b1[2] = {r2, r3};
                mma_f16(acc[0][np * 2],     a[0], b0);
                mma_f16(acc[1][np * 2],     a[1], b0);
                mma_f16(acc[0][np * 2 + 1], a[0], b1);
                mma_f16(acc[1][np * 2 + 1], a[1], b1);
            }
        }
        if (more) stA(buf ^ 1);
        cp_wait0();
        __syncthreads();
    }

    // fused epilogue: att = S * w1/w2
    const size_t rowbase = (size_t)b * NSEQ + j0;
    #pragma unroll
    for (int mt = 0; mt < 2; ++mt) {
        const int r0 = wm * 32 + mt * 16 + g;
        #pragma unroll
        for (int nt = 0; nt < 8; ++nt) {
            const int e = wn * 32 + nt * 4 + tg;
            const size_t i0 = (rowbase + r0) * 128 + e;
            const size_t i1 = (rowbase + r0 + 8) * 128 + e;
            g_att[i0] = g_S[i0] * __fdividef(acc[mt][nt][0], acc[mt][nt][1]);
            g_att[i1] = g_S[i1] * __fdividef(acc[mt][nt][2], acc[mt][nt][3]);
        }
    }
}

// ---------------- small GEMM (tf32 mma) ----------------
// mode 1: +res  2: relu(+bias)  3: +bias+res
__global__ __launch_bounds__(256)
void gemm_small_kernel(const float* __restrict__ A, const float* __restrict__ B,
                       float* __restrict__ C, int K, int N, int mode,
                       const float* __restrict__ bias, const float* __restrict__ res) {
    __shared__ float As[128 * 36];
    __shared__ float Bs[32 * 72];
    const int m0 = blockIdx.x * 128;
    const int n0 = blockIdx.y * 64;
    const int tid = threadIdx.x, lane = tid & 31, warp = tid >> 5;
    const int wm = warp >> 1, wn = warp & 1;
    const int g = lane >> 2, tg = lane & 3;

    float acc[2][4][4];
    #pragma unroll
    for (int i = 0; i < 2; i++)
        #pragma unroll
        for (int j = 0; j < 4; j++)
            #pragma unroll
            for (int r = 0; r < 4; r++) acc[i][j][r] = 0.0f;

    for (int k0 = 0; k0 < K; k0 += 32) {
        #pragma unroll
        for (int i = 0; i < 4; i++) {
            int id = tid + i * 256;
            int m = id >> 3, c = (id & 7) << 2;
            float4 v = *reinterpret_cast<const float4*>(A + (size_t)(m0 + m) * K + k0 + c);
            float* p = As + m * 36 + c;
            p[0] = tf32r(v.x); p[1] = tf32r(v.y); p[2] = tf32r(v.z); p[3] = tf32r(v.w);
        }
        #pragma unroll
        for (int i = 0; i < 2; i++) {
            int id = tid + i * 256;
            int k = id >> 4, c = (id & 15) << 2;
            float4 v = *reinterpret_cast<const float4*>(B + (size_t)(k0 + k) * N + n0 + c);
            float* p = Bs + k * 72 + c;
            p[0] = tf32r(v.x); p[1] = tf32r(v.y); p[2] = tf32r(v.z); p[3] = tf32r(v.w);
        }
        __syncthreads();
        #pragma unroll
        for (int ks = 0; ks < 4; ++ks) {
            const int kr = ks * 8 + tg;
            float a[2][4];
            #pragma unroll
            for (int mt = 0; mt < 2; ++mt) {
                int m = wm * 32 + mt * 16 + g;
                a[mt][0] = As[m * 36 + kr];
                a[mt][1] = As[(m + 8) * 36 + kr];
                a[mt][2] = As[m * 36 + kr + 4];
                a[mt][3] = As[(m + 8) * 36 + kr + 4];
            }
            float bb[4][2];
            #pragma unroll
            for (int nt = 0; nt < 4; ++nt) {
                int n = wn * 32 + nt * 8 + g;
                bb[nt][0] = Bs[kr * 72 + n];
                bb[nt][1] = Bs[(kr + 4) * 72 + n];
            }
            #pragma unroll
            for (int mt = 0; mt < 2; ++mt)
                #pragma unroll
                for (int nt = 0; nt < 4; ++nt)
                    mma_tf32(acc[mt][nt], a[mt], bb[nt]);
        }
        __syncthreads();
    }

    #pragma unroll
    for (int mt = 0; mt < 2; ++mt) {
        const int row0 = m0 + wm * 32 + mt * 16 + g;
        #pragma unroll
        for (int nt = 0; nt < 4; ++nt) {
            const int col = n0 + wn * 32 + nt * 8 + tg * 2;
            #pragma unroll
            for (int h = 0; h < 2; ++h) {
                const int row = row0 + h * 8;
                float v0 = acc[mt][nt][h * 2 + 0];
                float v1 = acc[mt][nt][h * 2 + 1];
                if (mode == 1) {
                    v0 += res[(size_t)row * N + col];
                    v1 += res[(size_t)row * N + col + 1];
                } else if (mode == 2) {
                    v0 = fmaxf(v0 + bias[col], 0.0f);
                    v1 = fmaxf(v1 + bias[col + 1], 0.0f);
                } else if (mode == 3) {
                    v0 += bias[col]     + res[(size_t)row * N + col];
                    v1 += bias[col + 1] + res[(size_t)row * N + col + 1];
                }
                C[(size_t)row * N + col]     = v0;
                C[(size_t)row * N + col + 1] = v1;
            }
        }
    }
}

// ---------------- launch ----------------
extern "C" void kernel_launch(void* const* d_in, const int* in_sizes, int n_in,
                              void* d_out, int out_size) {
    const float* x     = (const float*)d_in[0];
    const float* dis   = (const float*)d_in[1];
    const float* g_in  = (const float*)d_in[2];
    const float* g_po  = (const float*)d_in[3];
    const float* Wq    = (const float*)d_in[4];
    const float* Wk    = (const float*)d_in[5];
    const float* Wv    = (const float*)d_in[6];
    const float* alpha = (const float*)d_in[7];
    const float* Wo    = (const float*)d_in[8];
    const float* W1    = (const float*)d_in[9];
    const float* b1    = (const float*)d_in[10];
    const float* W2    = (const float*)d_in[11];
    const float* b2    = (const float*)d_in[12];
    float* out = (float*)d_out;

    float *p_h, *p_att, *p_out1, *p_h2, *p_t;
    cudaGetSymbolAddress((void**)&p_h,    g_h);
    cudaGetSymbolAddress((void**)&p_att,  g_att);
    cudaGetSymbolAddress((void**)&p_out1, g_out1);
    cudaGetSymbolAddress((void**)&p_h2,   g_h2);
    cudaGetSymbolAddress((void**)&p_t,    g_t);

    cudaFuncSetAttribute(big_kernel,
                         cudaFuncAttributeMaxDynamicSharedMemorySize, BIG_SMEM);

    // launches 0-3: rmsnorm quarters (so big_kernel is launch #5 for ncu -s 5)
    const int qtok = NTOK / 4;
    for (int q = 0; q < 4; ++q)
        rmsnorm_kernel<<<qtok / 8, 256>>>(x, g_in, p_h, q * qtok);
    // launch 4: fused QKV (+sigmoid/exp epilogue -> g_S, g_Xh)
    qkv_kernel<<<dim3(NTOK / 128, 4), 256>>>(p_h, Wq, Wk, Wv);
    // launch 5: big GEMM + fused att epilogue
    big_kernel<<<dim3(NSEQ / 128, NB), 512, BIG_SMEM>>>(dis, alpha);
    // out1 = x + att @ Wo
    gemm_small_kernel<<<dim3(NTOK / 128, 2), 256>>>(p_att, Wo, p_out1,
                                                    128, 128, 1, nullptr, x);
    rmsnorm_kernel<<<NTOK / 8, 256>>>(p_out1, g_po, p_h2, 0);
    gemm_small_kernel<<<dim3(NTOK / 128, 8), 256>>>(p_h2, W1, p_t,
                                                    128, 512, 2, b1, nullptr);
    gemm_small_kernel<<<dim3(NTOK / 128, 2), 256>>>(p_t, W2, out,
                                                    512, 128, 3, b2, p_out1);
}

// round 6
// speedup vs baseline: 1.5549x; 1.1341x over previous
#include <cuda_runtime.h>
#include <cuda_fp16.h>
#include <cstdint>
#include <cstddef>

#define NB     4
#define NSEQ   4096
#define EDIM   128
#define FFD    512
#define NTOK   (NB * NSEQ)

// ---------------- scratch ----------------
__device__ float  g_h   [NTOK * EDIM];
__device__ float  g_S   [NTOK * EDIM];
__device__ __half g_Xh  [NTOK * 256];     // [t][256]: 2e=exp(k)*v, 2e+1=exp(k)
__device__ float  g_att [NTOK * EDIM];
__device__ float  g_out1[NTOK * EDIM];
__device__ float  g_h2  [NTOK * EDIM];
__device__ float  g_t   [NTOK * FFD];

// ---------------- helpers ----------------
__device__ __forceinline__ float tf32r(float x) {
    uint32_t u;
    asm("cvt.rna.tf32.f32 %0, %1;" : "=r"(u) : "f"(x));
    return __uint_as_float(u);
}
__device__ __forceinline__ void mma_tf32(float* c, const float* a, const float* b) {
    asm volatile(
        "mma.sync.aligned.m16n8k8.row.col.f32.tf32.tf32.f32 "
        "{%0,%1,%2,%3}, {%4,%5,%6,%7}, {%8,%9}, {%0,%1,%2,%3};\n"
        : "+f"(c[0]), "+f"(c[1]), "+f"(c[2]), "+f"(c[3])
        : "r"(__float_as_uint(a[0])), "r"(__float_as_uint(a[1])),
          "r"(__float_as_uint(a[2])), "r"(__float_as_uint(a[3])),
          "r"(__float_as_uint(b[0])), "r"(__float_as_uint(b[1])));
}
__device__ __forceinline__ void mma_f16(float* c, const uint32_t* a, const uint32_t* b) {
    asm volatile(
        "mma.sync.aligned.m16n8k16.row.col.f32.f16.f16.f32 "
        "{%0,%1,%2,%3}, {%4,%5,%6,%7}, {%8,%9}, {%0,%1,%2,%3};\n"
        : "+f"(c[0]), "+f"(c[1]), "+f"(c[2]), "+f"(c[3])
        : "r"(a[0]), "r"(a[1]), "r"(a[2]), "r"(a[3]), "r"(b[0]), "r"(b[1]));
}
__device__ __forceinline__ void cp16(void* s, const void* gp) {
    uint32_t sa = (uint32_t)__cvta_generic_to_shared(s);
    asm volatile("cp.async.cg.shared.global [%0], [%1], 16;\n" :: "r"(sa), "l"(gp));
}
__device__ __forceinline__ void cp_commit() {
    asm volatile("cp.async.commit_group;\n" ::: "memory");
}
__device__ __forceinline__ void cp_wait1() {
    asm volatile("cp.async.wait_group 1;\n" ::: "memory");
}
__device__ __forceinline__ void ldmx4(uint32_t& r0, uint32_t& r1, uint32_t& r2,
                                      uint32_t& r3, uint32_t addr) {
    asm volatile("ldmatrix.sync.aligned.m8n8.x4.shared.b16 {%0,%1,%2,%3}, [%4];"
                 : "=r"(r0), "=r"(r1), "=r"(r2), "=r"(r3) : "r"(addr));
}
__device__ __forceinline__ void ldmx4t(uint32_t& r0, uint32_t& r1, uint32_t& r2,
                                       uint32_t& r3, uint32_t addr) {
    asm volatile("ldmatrix.sync.aligned.m8n8.x4.trans.shared.b16 {%0,%1,%2,%3}, [%4];"
                 : "=r"(r0), "=r"(r1), "=r"(r2), "=r"(r3) : "r"(addr));
}
__device__ __forceinline__ uint32_t smem_u32(const void* p) {
    return (uint32_t)__cvta_generic_to_shared(p);
}

// ---------------- rmsnorm ----------------
__global__ void rmsnorm_kernel(const float* __restrict__ x,
                               const float* __restrict__ gw,
                               float* __restrict__ y) {
    int warp = (blockIdx.x * blockDim.x + threadIdx.x) >> 5;
    int lane = threadIdx.x & 31;
    if (warp >= NTOK) return;
    float4 v = reinterpret_cast<const float4*>(x + (size_t)warp * EDIM)[lane];
    float ss = v.x * v.x + v.y * v.y + v.z * v.z + v.w * v.w;
    #pragma unroll
    for (int o = 16; o > 0; o >>= 1) ss += __shfl_xor_sync(0xffffffffu, ss, o);
    float s = rsqrtf(ss * (1.0f / 128.0f) + 1e-6f);
    float4 g4 = reinterpret_cast<const float4*>(gw)[lane];
    float4 o4 = make_float4(v.x * s * g4.x, v.y * s * g4.y, v.z * s * g4.z, v.w * s * g4.w);
    reinterpret_cast<float4*>(y + (size_t)warp * EDIM)[lane] = o4;
}

// ---------------------------------------------------------------------------
// Fused QKV GEMM: one block = 128 tokens x 32 cols of q,k,v simultaneously.
// Epilogue: g_S = sigmoid(q); g_Xh[t][2e,2e+1] = half(exp(k)*v), half(exp(k)).
// ---------------------------------------------------------------------------
__global__ __launch_bounds__(256)
void qkv_kernel(const float* __restrict__ h, const float* __restrict__ Wq,
                const float* __restrict__ Wk, const float* __restrict__ Wv) {
    __shared__ float As[128 * 36];
    __shared__ float Bs[3][32 * 36];
    const int m0 = blockIdx.x * 128;
    const int j0 = blockIdx.y * 32;
    const int tid = threadIdx.x, lane = tid & 31, warp = tid >> 5;
    const int wm = warp >> 1, wn = warp & 1;    // 4 x 2 warps, 32m x 16n each
    const int g = lane >> 2, tg = lane & 3;

    float acc[3][2][2][4];
    #pragma unroll
    for (int w = 0; w < 3; w++)
        #pragma unroll
        for (int i = 0; i < 2; i++)
            #pragma unroll
            for (int j = 0; j < 2; j++)
                #pragma unroll
                for (int r = 0; r < 4; r++) acc[w][i][j][r] = 0.0f;

    const float* Wp[3] = {Wq, Wk, Wv};

    for (int k0 = 0; k0 < 128; k0 += 32) {
        #pragma unroll
        for (int i = 0; i < 4; i++) {
            int id = tid + i * 256;
            int m = id >> 3, c = (id & 7) << 2;
            float4 v = *reinterpret_cast<const float4*>(h + (size_t)(m0 + m) * 128 + k0 + c);
            float* p = As + m * 36 + c;
            p[0] = tf32r(v.x); p[1] = tf32r(v.y); p[2] = tf32r(v.z); p[3] = tf32r(v.w);
        }
        {
            int k = tid >> 3, c = (tid & 7) << 2;
            #pragma unroll
            for (int w = 0; w < 3; w++) {
                float4 v = *reinterpret_cast<const float4*>(Wp[w] + (size_t)(k0 + k) * 128 + j0 + c);
                float* p = Bs[w] + k * 36 + c;
                p[0] = tf32r(v.x); p[1] = tf32r(v.y); p[2] = tf32r(v.z); p[3] = tf32r(v.w);
            }
        }
        __syncthreads();
        #pragma unroll
        for (int ks = 0; ks < 4; ++ks) {
            const int kr = ks * 8 + tg;
            float a[2][4];
            #pragma unroll
            for (int mt = 0; mt < 2; ++mt) {
                int m = wm * 32 + mt * 16 + g;
                a[mt][0] = As[m * 36 + kr];
                a[mt][1] = As[(m + 8) * 36 + kr];
                a[mt][2] = As[m * 36 + kr + 4];
                a[mt][3] = As[(m + 8) * 36 + kr + 4];
            }
            #pragma unroll
            for (int w = 0; w < 3; w++) {
                #pragma unroll
                for (int nt = 0; nt < 2; ++nt) {
                    int n = wn * 16 + nt * 8 + g;
                    float bb[2];
                    bb[0] = Bs[w][kr * 36 + n];
                    bb[1] = Bs[w][(kr + 4) * 36 + n];
                    mma_tf32(acc[w][0][nt], a[0], bb);
                    mma_tf32(acc[w][1][nt], a[1], bb);
                }
            }
        }
        __syncthreads();
    }

    // epilogue
    #pragma unroll
    for (int mt = 0; mt < 2; ++mt) {
        #pragma unroll
        for (int nt = 0; nt < 2; ++nt) {
            const int col = j0 + wn * 16 + nt * 8 + tg * 2;
            #pragma unroll
            for (int hh = 0; hh < 2; ++hh) {
                const int row = m0 + wm * 32 + mt * 16 + g + hh * 8;
                float q0 = acc[0][mt][nt][hh * 2], q1 = acc[0][mt][nt][hh * 2 + 1];
                float k0v = acc[1][mt][nt][hh * 2], k1v = acc[1][mt][nt][hh * 2 + 1];
                float v0 = acc[2][mt][nt][hh * 2], v1 = acc[2][mt][nt][hh * 2 + 1];
                float2 s2 = make_float2(1.0f / (1.0f + expf(-q0)),
                                        1.0f / (1.0f + expf(-q1)));
                *reinterpret_cast<float2*>(g_S + (size_t)row * 128 + col) = s2;
                float kw0 = expf(k0v), kw1 = expf(k1v);
                __half2 h0 = __floats2half2_rn(kw0 * v0, kw0);
                __half2 h1 = __floats2half2_rn(kw1 * v1, kw1);
                uint2 u;
                u.x = *reinterpret_cast<uint32_t*>(&h0);
                u.y = *reinterpret_cast<uint32_t*>(&h1);
                *reinterpret_cast<uint2*>(g_Xh + (size_t)row * 256 + 2 * col) = u;
            }
        }
    }
}

// ---------------------------------------------------------------------------
// Big GEMM (fp16 m16n8k16), per batch: D[j,n] = sum_i exp(-coef*dis[i,j])*Xh[i,n]
// M=128/blk, N=256, BK=32. A: reg-transposed exp() into [m][40] half smem
// (80B stride -> conflict-free ldmatrix), fragments via ldmatrix.x4.
// B: 3-stage cp.async pipeline, [k][264] rows, fragments via ldmatrix.x4.trans.
// Fused epilogue: att = sigmoid(q) * w1/w2.
// ---------------------------------------------------------------------------
#define AH_STR 40
#define AH_BUF 5120            // 128*40 halfs
#define BH_STR 264
#define BH_BUF 8448            // 32*264 halfs
#define BH_OFF 10240           // halfs (after 2 A buffers)
#define BIG_SMEM 71168         // (10240 + 3*8448) * 2 bytes

__global__ __launch_bounds__(512, 1)
void big_kernel(const float* __restrict__ dis, const float* __restrict__ alphap) {
    extern __shared__ __half smh[];
    __half* Ah = smh;
    __half* Bh = smh + BH_OFF;
    const uint32_t smb = smem_u32(smh);

    const int tid = threadIdx.x, lane = tid & 31, warp = tid >> 5;
    const int wm = warp >> 2, wn = warp & 3;     // 4 x 4 warps: 32m x 64n
    const int g = lane >> 2, tg = lane & 3;
    const int b = blockIdx.y, j0 = blockIdx.x * 128;
    const float coef = 12.0f * alphap[0];
    const float* Ag = dis + (size_t)b * NSEQ * NSEQ;
    const __half* Xg = g_Xh + (size_t)b * NSEQ * 256;

    const int am = tid & 127, ar4 = (tid >> 7) << 2;   // A stage: col m, 4 k-rows

    // ldmatrix address offsets (in halfs, within a buffer)
    const int lr = lane & 7, sel = lane >> 3;
    uint32_t aoff[2];
    #pragma unroll
    for (int mt = 0; mt < 2; ++mt)
        aoff[mt] = (uint32_t)((wm * 32 + mt * 16 + (sel & 1) * 8 + lr) * AH_STR +
                              (sel >> 1) * 8);
    const uint32_t lm_half = (uint32_t)((lane & 15) * BH_STR + wn * 64 + ((lane >> 4) << 3));

    float ra[2][4];
    float acc[2][8][4];
    #pragma unroll
    for (int i = 0; i < 2; i++)
        #pragma unroll
        for (int j = 0; j < 8; j++)
            #pragma unroll
            for (int r = 0; r < 4; r++) acc[i][j][r] = 0.0f;

    auto ldA = [&](int k0) {
        #pragma unroll
        for (int it = 0; it < 2; ++it) {
            const float* p = Ag + (size_t)(k0 + it * 16 + ar4) * NSEQ + j0 + am;
            ra[it][0] = p[0]; ra[it][1] = p[NSEQ];
            ra[it][2] = p[2 * NSEQ]; ra[it][3] = p[3 * NSEQ];
        }
    };
    auto stA = [&](int buf) {
        __half* base = Ah + buf * AH_BUF + am * AH_STR;
        #pragma unroll
        for (int it = 0; it < 2; ++it) {
            __half2 h01 = __floats2half2_rn(__expf(-coef * ra[it][0]),
                                            __expf(-coef * ra[it][1]));
            __half2 h23 = __floats2half2_rn(__expf(-coef * ra[it][2]),
                                            __expf(-coef * ra[it][3]));
            uint2 u;
            u.x = *reinterpret_cast<uint32_t*>(&h01);
            u.y = *reinterpret_cast<uint32_t*>(&h23);
            *reinterpret_cast<uint2*>(base + it * 16 + ar4) = u;
        }
    };
    auto cpB = [&](int stage, int k0) {
        #pragma unroll
        for (int it = 0; it < 2; ++it) {
            int ch = tid + it * 512;
            int row = ch >> 5, cc = (ch & 31) << 3;
            cp16(Bh + stage * BH_BUF + row * BH_STR + cc,
                 Xg + (size_t)(k0 + row) * 256 + cc);
        }
    };

    // prologue: 2 B stages in flight, A buffer 0 staged
    cpB(0, 0);  cp_commit();
    cpB(1, 32); cp_commit();
    ldA(0);
    stA(0);
    cp_wait1();                 // stage 0 complete
    __syncthreads();

    for (int kt = 0; kt < 128; ++kt) {
        const int sbuf = kt % 3;
        const int abuf = kt & 1;
        if (kt + 2 < 128) { cpB((kt + 2) % 3, (kt + 2) * 32); cp_commit(); }
        if (kt + 1 < 128) ldA((kt + 1) * 32);

        const uint32_t abase = smb + 2u * (abuf * AH_BUF);
        const uint32_t bbase = smb + 2u * (BH_OFF + sbuf * BH_BUF + lm_half);
        #pragma unroll
        for (int ks = 0; ks < 2; ++ks) {
            const int kb = ks * 16;
            uint32_t a[2][4];
            #pragma unroll
            for (int mt = 0; mt < 2; ++mt)
                ldmx4(a[mt][0], a[mt][1], a[mt][2], a[mt][3],
                      abase + 2u * (aoff[mt] + kb));
            #pragma unroll
            for (int np = 0; np < 4; ++np) {
                uint32_t r0, r1, r2, r3;
                ldmx4t(r0, r1, r2, r3, bbase + 2u * (kb * BH_STR + np * 16));
                uint32_t b0[2] = {r0, r1}, b1[2] = {r2, r3};
                mma_f16(acc[0][np * 2],     a[0], b0);
                mma_f16(acc[1][np * 2],     a[1], b0);
                mma_f16(acc[0][np * 2 + 1], a[0], b1);
                mma_f16(acc[1][np * 2 + 1], a[1], b1);
            }
        }
        if (kt + 1 < 128) stA(abuf ^ 1);
        cp_wait1();             // next B stage complete
        __syncthreads();
    }

    // fused epilogue: att = S * w1/w2
    const size_t rowbase = (size_t)b * NSEQ + j0;
    #pragma unroll
    for (int mt = 0; mt < 2; ++mt) {
        const int r0 = wm * 32 + mt * 16 + g;
        #pragma unroll
        for (int nt = 0; nt < 8; ++nt) {
            const int e = wn * 32 + nt * 4 + tg;
            const size_t i0 = (rowbase + r0) * 128 + e;
            const size_t i1 = (rowbase + r0 + 8) * 128 + e;
            g_att[i0] = g_S[i0] * __fdividef(acc[mt][nt][0], acc[mt][nt][1]);
            g_att[i1] = g_S[i1] * __fdividef(acc[mt][nt][2], acc[mt][nt][3]);
        }
    }
}

// ---------------- small GEMM (tf32 mma) ----------------
// mode 1: +res  2: relu(+bias)  3: +bias+res
__global__ __launch_bounds__(256)
void gemm_small_kernel(const float* __restrict__ A, const float* __restrict__ B,
                       float* __restrict__ C, int K, int N, int mode,
                       const float* __restrict__ bias, const float* __restrict__ res) {
    __shared__ float As[128 * 36];
    __shared__ float Bs[32 * 72];
    const int m0 = blockIdx.x * 128;
    const int n0 = blockIdx.y * 64;
    const int tid = threadIdx.x, lane = tid & 31, warp = tid >> 5;
    const int wm = warp >> 1, wn = warp & 1;
    const int g = lane >> 2, tg = lane & 3;

    float acc[2][4][4];
    #pragma unroll
    for (int i = 0; i < 2; i++)
        #pragma unroll
        for (int j = 0; j < 4; j++)
            #pragma unroll
            for (int r = 0; r < 4; r++) acc[i][j][r] = 0.0f;

    for (int k0 = 0; k0 < K; k0 += 32) {
        #pragma unroll
        for (int i = 0; i < 4; i++) {
            int id = tid + i * 256;
            int m = id >> 3, c = (id & 7) << 2;
            float4 v = *reinterpret_cast<const float4*>(A + (size_t)(m0 + m) * K + k0 + c);
            float* p = As + m * 36 + c;
            p[0] = tf32r(v.x); p[1] = tf32r(v.y); p[2] = tf32r(v.z); p[3] = tf32r(v.w);
        }
        #pragma unroll
        for (int i = 0; i < 2; i++) {
            int id = tid + i * 256;
            int k = id >> 4, c = (id & 15) << 2;
            float4 v = *reinterpret_cast<const float4*>(B + (size_t)(k0 + k) * N + n0 + c);
            float* p = Bs + k * 72 + c;
            p[0] = tf32r(v.x); p[1] = tf32r(v.y); p[2] = tf32r(v.z); p[3] = tf32r(v.w);
        }
        __syncthreads();
        #pragma unroll
        for (int ks = 0; ks < 4; ++ks) {
            const int kr = ks * 8 + tg;
            float a[2][4];
            #pragma unroll
            for (int mt = 0; mt < 2; ++mt) {
                int m = wm * 32 + mt * 16 + g;
                a[mt][0] = As[m * 36 + kr];
                a[mt][1] = As[(m + 8) * 36 + kr];
                a[mt][2] = As[m * 36 + kr + 4];
                a[mt][3] = As[(m + 8) * 36 + kr + 4];
            }
            float bb[4][2];
            #pragma unroll
            for (int nt = 0; nt < 4; ++nt) {
                int n = wn * 32 + nt * 8 + g;
                bb[nt][0] = Bs[kr * 72 + n];
                bb[nt][1] = Bs[(kr + 4) * 72 + n];
            }
            #pragma unroll
            for (int mt = 0; mt < 2; ++mt)
                #pragma unroll
                for (int nt = 0; nt < 4; ++nt)
                    mma_tf32(acc[mt][nt], a[mt], bb[nt]);
        }
        __syncthreads();
    }

    #pragma unroll
    for (int mt = 0; mt < 2; ++mt) {
        const int row0 = m0 + wm * 32 + mt * 16 + g;
        #pragma unroll
        for (int nt = 0; nt < 4; ++nt) {
            const int col = n0 + wn * 32 + nt * 8 + tg * 2;
            #pragma unroll
            for (int h = 0; h < 2; ++h) {
                const int row = row0 + h * 8;
                float v0 = acc[mt][nt][h * 2 + 0];
                float v1 = acc[mt][nt][h * 2 + 1];
                if (mode == 1) {
                    v0 += res[(size_t)row * N + col];
                    v1 += res[(size_t)row * N + col + 1];
                } else if (mode == 2) {
                    v0 = fmaxf(v0 + bias[col], 0.0f);
                    v1 = fmaxf(v1 + bias[col + 1], 0.0f);
                } else if (mode == 3) {
                    v0 += bias[col]     + res[(size_t)row * N + col];
                    v1 += bias[col + 1] + res[(size_t)row * N + col + 1];
                }
                C[(size_t)row * N + col]     = v0;
                C[(size_t)row * N + col + 1] = v1;
            }
        }
    }
}

// ---------------- launch ----------------
extern "C" void kernel_launch(void* const* d_in, const int* in_sizes, int n_in,
                              void* d_out, int out_size) {
    const float* x     = (const float*)d_in[0];
    const float* dis   = (const float*)d_in[1];
    const float* g_in  = (const float*)d_in[2];
    const float* g_po  = (const float*)d_in[3];
    const float* Wq    = (const float*)d_in[4];
    const float* Wk    = (const float*)d_in[5];
    const float* Wv    = (const float*)d_in[6];
    const float* alpha = (const float*)d_in[7];
    const float* Wo    = (const float*)d_in[8];
    const float* W1    = (const float*)d_in[9];
    const float* b1    = (const float*)d_in[10];
    const float* W2    = (const float*)d_in[11];
    const float* b2    = (const float*)d_in[12];
    float* out = (float*)d_out;

    float *p_h, *p_att, *p_out1, *p_h2, *p_t;
    cudaGetSymbolAddress((void**)&p_h,    g_h);
    cudaGetSymbolAddress((void**)&p_att,  g_att);
    cudaGetSymbolAddress((void**)&p_out1, g_out1);
    cudaGetSymbolAddress((void**)&p_h2,   g_h2);
    cudaGetSymbolAddress((void**)&p_t,    g_t);

    cudaFuncSetAttribute(big_kernel,
                         cudaFuncAttributeMaxDynamicSharedMemorySize, BIG_SMEM);

    rmsnorm_kernel<<<NTOK / 8, 256>>>(x, g_in, p_h);
    qkv_kernel<<<dim3(NTOK / 128, 4), 256>>>(p_h, Wq, Wk, Wv);
    big_kernel<<<dim3(NSEQ / 128, NB), 512, BIG_SMEM>>>(dis, alpha);
    gemm_small_kernel<<<dim3(NTOK / 128, 2), 256>>>(p_att, Wo, p_out1,
                                                    128, 128, 1, nullptr, x);
    rmsnorm_kernel<<<NTOK / 8, 256>>>(p_out1, g_po, p_h2);
    gemm_small_kernel<<<dim3(NTOK / 128, 8), 256>>>(p_h2, W1, p_t,
                                                    128, 512, 2, b1, nullptr);
    gemm_small_kernel<<<dim3(NTOK / 128, 2), 256>>>(p_t, W2, out,
                                                    512, 128, 3, b2, p_out1);
}